// round 3
// baseline (speedup 1.0000x reference)
#include <cuda_runtime.h>
#include <math.h>

// ---------------------------------------------------------------------------
// SFFM: pre-GEMM + rownorm -> resettable complex scan -> mix/skip GEMM
// Sizes fixed by the problem.
// ---------------------------------------------------------------------------
#define TT      8192
#define DIN     1024
#define DOUT    1024
#define MTR     64
#define CCT     16
#define NCH     1024          // MTR*CCT channels
#define CHUNK   64
#define NCHUNK  128           // TT/CHUNK
#define DMIX    2048          // 2*MTR*CCT
#define KTOT    (DMIX + DIN)  // 3072 combined K for the output GEMM

// Scratch (static __device__ arrays: no runtime allocation allowed)
__device__ float g_pre[TT * MTR];          // normalized pre activations [T,64]
__device__ float g_Bre[NCHUNK * NCH];      // per-chunk transfer B (local final state)
__device__ float g_Bim[NCHUNK * NCH];
__device__ float g_cRe[NCHUNK * NCH];      // per-chunk incoming carry state
__device__ float g_cIm[NCHUNK * NCH];
__device__ int   g_any[NCHUNK];            // chunk contains a reset?
__device__ float g_zin[TT * DMIX];         // [T, 2048] scan output, mix-GEMM input

// ---------------------------------------------------------------------------
// K1: pre = rownorm(x @ W_pre^T + b_pre).  64x64 tile per block, K=1024.
// grid = 128 blocks of 256 threads, 4x4 microtile.
// ---------------------------------------------------------------------------
__global__ __launch_bounds__(256) void k_pre(const float* __restrict__ x,
                                             const float* __restrict__ Wp,
                                             const float* __restrict__ bp) {
    __shared__ float xs[32][65];
    __shared__ float ws[32][65];
    __shared__ float nrm[64];
    const int tid = threadIdx.x;
    const int ty = tid >> 4, tx = tid & 15;
    const int row0 = blockIdx.x * 64;

    float acc[4][4];
#pragma unroll
    for (int i = 0; i < 4; i++)
#pragma unroll
        for (int j = 0; j < 4; j++) acc[i][j] = 0.f;

    for (int k0 = 0; k0 < DIN; k0 += 32) {
#pragma unroll
        for (int r = 0; r < 8; r++) {
            int idx = tid + r * 256;      // 0..2047 over 64x32 tile
            int m = idx >> 5, k = idx & 31;
            xs[k][m] = x[(size_t)(row0 + m) * DIN + k0 + k];
            ws[k][m] = Wp[(size_t)m * DIN + k0 + k];
        }
        __syncthreads();
#pragma unroll
        for (int kk = 0; kk < 32; kk++) {
            float av[4], bv[4];
#pragma unroll
            for (int i = 0; i < 4; i++) av[i] = xs[kk][ty * 4 + i];
#pragma unroll
            for (int j = 0; j < 4; j++) bv[j] = ws[kk][tx * 4 + j];
#pragma unroll
            for (int i = 0; i < 4; i++)
#pragma unroll
                for (int j = 0; j < 4; j++) acc[i][j] += av[i] * bv[j];
        }
        __syncthreads();
    }
    // bias (before normalization, matching reference)
#pragma unroll
    for (int j = 0; j < 4; j++) {
        float b = bp[tx * 4 + j];
#pragma unroll
        for (int i = 0; i < 4; i++) acc[i][j] += b;
    }
    // row norms across the 64 outputs (all inside this block)
    if (tid < 64) nrm[tid] = 0.f;
    __syncthreads();
#pragma unroll
    for (int i = 0; i < 4; i++) {
        float s = 0.f;
#pragma unroll
        for (int j = 0; j < 4; j++) s += acc[i][j] * acc[i][j];
        atomicAdd(&nrm[ty * 4 + i], s);
    }
    __syncthreads();
#pragma unroll
    for (int i = 0; i < 4; i++) {
        float inv = 1.0f / (1e-6f + sqrtf(nrm[ty * 4 + i]));
#pragma unroll
        for (int j = 0; j < 4; j++)
            g_pre[(size_t)(row0 + ty * 4 + i) * MTR + tx * 4 + j] = acc[i][j] * inv;
    }
}

// ---------------------------------------------------------------------------
// K2a: per-chunk local scan from S=0; store transfer (B, anyStart).
// block = one chunk of 64 timesteps; 256 threads x 4 channels each.
// Recurrence: S_t = (start_t ? 0 : gamma * S_{t-1}) + pre_t  (pre added to Re)
// ---------------------------------------------------------------------------
__global__ __launch_bounds__(256) void k_chunk(const int* __restrict__ start,
                                               const float* __restrict__ a,
                                               const float* __restrict__ bfreq) {
    __shared__ float sp[CHUNK][MTR];
    __shared__ int ss[CHUNK];
    __shared__ int sAny;
    const int tid = threadIdx.x;
    const int ck = blockIdx.x;
    const int t0 = ck * CHUNK;

    for (int idx = tid; idx < CHUNK * MTR; idx += 256)
        sp[idx >> 6][idx & 63] = g_pre[(size_t)(t0 + (idx >> 6)) * MTR + (idx & 63)];
    if (tid < CHUNK) ss[tid] = (start[t0 + tid] != 0);
    if (tid == 0) sAny = 0;
    __syncthreads();
    if (tid < CHUNK && ss[tid]) atomicOr(&sAny, 1);

    const int m = tid >> 2;
    const float gmag = expf(-fabsf(a[m]));
    float gre[4], gim[4], Sre[4], Sim[4];
#pragma unroll
    for (int q = 0; q < 4; q++) {
        int c = ((tid & 3) << 2) + q;
        float sv, cv; sincosf(bfreq[c], &sv, &cv);
        gre[q] = gmag * cv; gim[q] = gmag * sv;
        Sre[q] = 0.f; Sim[q] = 0.f;
    }
    for (int t = 0; t < CHUNK; t++) {
        float p = sp[t][m];
        float keep = ss[t] ? 0.f : 1.f;
#pragma unroll
        for (int q = 0; q < 4; q++) {
            float r  = keep * (gre[q] * Sre[q] - gim[q] * Sim[q]) + p;
            float im = keep * (gre[q] * Sim[q] + gim[q] * Sre[q]);
            Sre[q] = r; Sim[q] = im;
        }
    }
#pragma unroll
    for (int q = 0; q < 4; q++) {
        int ch = tid * 4 + q;
        g_Bre[(size_t)ck * NCH + ch] = Sre[q];
        g_Bim[(size_t)ck * NCH + ch] = Sim[q];
    }
    __syncthreads();
    if (tid == 0) g_any[ck] = sAny;
}

// ---------------------------------------------------------------------------
// K2b: sequential chain over 128 chunks (1 block, 1024 threads = 1 channel each).
// S_out = (anyStart ? 0 : gamma^64 * S_in) + B.  Also writes final carry state.
// ---------------------------------------------------------------------------
__global__ __launch_bounds__(1024) void k_chain(const float* __restrict__ s_re0,
                                                const float* __restrict__ s_im0,
                                                const float* __restrict__ a,
                                                const float* __restrict__ bfreq,
                                                float* stateOut) {
    const int ch = threadIdx.x;
    const int m = ch >> 4, c = ch & 15;
    const float Amag = expf(-64.f * fabsf(a[m]));
    float sv, cv; sincosf(64.f * bfreq[c], &sv, &cv);
    const float Are = Amag * cv, Aim = Amag * sv;
    float Sre = s_re0[ch], Sim = s_im0[ch];
#pragma unroll 4
    for (int k = 0; k < NCHUNK; k++) {
        g_cRe[(size_t)k * NCH + ch] = Sre;
        g_cIm[(size_t)k * NCH + ch] = Sim;
        float br = g_Bre[(size_t)k * NCH + ch];
        float bi = g_Bim[(size_t)k * NCH + ch];
        float keep = g_any[k] ? 0.f : 1.f;
        float r  = keep * (Are * Sre - Aim * Sim) + br;
        float im = keep * (Are * Sim + Aim * Sre) + bi;
        Sre = r; Sim = im;
    }
    // final state, PLANAR float layout: [1024 real parts][1024 imag parts]
    stateOut[ch]       = Sre;
    stateOut[NCH + ch] = Sim;
}

// ---------------------------------------------------------------------------
// K2c: re-scan each chunk from its true incoming carry; emit z_in.
// z_in layout (matches concat([Re,Im],-1).reshape):
//   z_in[t, m*32 + c]      = Re(S[t,m,c])
//   z_in[t, m*32 + 16 + c] = Im(S[t,m,c])
// ---------------------------------------------------------------------------
__global__ __launch_bounds__(256) void k_emit(const int* __restrict__ start,
                                              const float* __restrict__ a,
                                              const float* __restrict__ bfreq) {
    __shared__ float sp[CHUNK][MTR];
    __shared__ int ss[CHUNK];
    const int tid = threadIdx.x;
    const int ck = blockIdx.x;
    const int t0 = ck * CHUNK;

    for (int idx = tid; idx < CHUNK * MTR; idx += 256)
        sp[idx >> 6][idx & 63] = g_pre[(size_t)(t0 + (idx >> 6)) * MTR + (idx & 63)];
    if (tid < CHUNK) ss[tid] = (start[t0 + tid] != 0);
    __syncthreads();

    const int m = tid >> 2;
    const float gmag = expf(-fabsf(a[m]));
    float gre[4], gim[4], Sre[4], Sim[4];
    int cidx[4];
#pragma unroll
    for (int q = 0; q < 4; q++) {
        int c = ((tid & 3) << 2) + q;
        cidx[q] = c;
        float sv, cv; sincosf(bfreq[c], &sv, &cv);
        gre[q] = gmag * cv; gim[q] = gmag * sv;
        int ch = tid * 4 + q;
        Sre[q] = g_cRe[(size_t)ck * NCH + ch];
        Sim[q] = g_cIm[(size_t)ck * NCH + ch];
    }
    for (int t = 0; t < CHUNK; t++) {
        float p = sp[t][m];
        float keep = ss[t] ? 0.f : 1.f;
        size_t rowbase = (size_t)(t0 + t) * DMIX + (size_t)m * 32;
#pragma unroll
        for (int q = 0; q < 4; q++) {
            float r  = keep * (gre[q] * Sre[q] - gim[q] * Sim[q]) + p;
            float im = keep * (gre[q] * Sim[q] + gim[q] * Sre[q]);
            Sre[q] = r; Sim[q] = im;
            g_zin[rowbase + cidx[q]]      = r;
            g_zin[rowbase + 16 + cidx[q]] = im;
        }
    }
}

// ---------------------------------------------------------------------------
// K3: out = z_in @ W_mix^T + x @ W_skip^T + b_mix + b_skip.
// One virtual GEMM, M=8192, N=1024, K=3072 (K-tiles 0..127 from z_in/W_mix,
// 128..191 from x/W_skip). 128x128x16 tiles, 256 threads, 8x8 microtile.
// ---------------------------------------------------------------------------
#define BM 128
#define BN 128
#define BK 16
__global__ __launch_bounds__(256, 2) void k_out(const float* __restrict__ x,
                                                const float* __restrict__ Wmix,
                                                const float* __restrict__ bmix,
                                                const float* __restrict__ Wskip,
                                                const float* __restrict__ bskip,
                                                float* __restrict__ out) {
    __shared__ float As[BK][BM + 4];
    __shared__ float Bs[BK][BN + 4];
    const int tid = threadIdx.x;
    const int ty = tid >> 4, tx = tid & 15;
    const int row0 = blockIdx.y * BM;
    const int col0 = blockIdx.x * BN;

    float acc[8][8];
#pragma unroll
    for (int i = 0; i < 8; i++)
#pragma unroll
        for (int j = 0; j < 8; j++) acc[i][j] = 0.f;

    for (int kt = 0; kt < KTOT; kt += BK) {
        if (kt < DMIX) {
#pragma unroll
            for (int r = 0; r < 2; r++) {
                int idx4 = tid + r * 256;       // 0..511 float4s over 128x16 tile
                int mm = idx4 >> 2;
                int kq = (idx4 & 3) << 2;
                float4 va = *(const float4*)(g_zin + (size_t)(row0 + mm) * DMIX + kt + kq);
                As[kq + 0][mm] = va.x; As[kq + 1][mm] = va.y;
                As[kq + 2][mm] = va.z; As[kq + 3][mm] = va.w;
                float4 vb = *(const float4*)(Wmix + (size_t)(col0 + mm) * DMIX + kt + kq);
                Bs[kq + 0][mm] = vb.x; Bs[kq + 1][mm] = vb.y;
                Bs[kq + 2][mm] = vb.z; Bs[kq + 3][mm] = vb.w;
            }
        } else {
            int k2 = kt - DMIX;
#pragma unroll
            for (int r = 0; r < 2; r++) {
                int idx4 = tid + r * 256;
                int mm = idx4 >> 2;
                int kq = (idx4 & 3) << 2;
                float4 va = *(const float4*)(x + (size_t)(row0 + mm) * DIN + k2 + kq);
                As[kq + 0][mm] = va.x; As[kq + 1][mm] = va.y;
                As[kq + 2][mm] = va.z; As[kq + 3][mm] = va.w;
                float4 vb = *(const float4*)(Wskip + (size_t)(col0 + mm) * DIN + k2 + kq);
                Bs[kq + 0][mm] = vb.x; Bs[kq + 1][mm] = vb.y;
                Bs[kq + 2][mm] = vb.z; Bs[kq + 3][mm] = vb.w;
            }
        }
        __syncthreads();
#pragma unroll
        for (int kk = 0; kk < BK; kk++) {
            const float4* Ar = (const float4*)&As[kk][ty * 8];
            const float4* Br = (const float4*)&Bs[kk][tx * 8];
            float4 a0 = Ar[0], a1 = Ar[1];
            float4 b0 = Br[0], b1 = Br[1];
            float av[8] = {a0.x, a0.y, a0.z, a0.w, a1.x, a1.y, a1.z, a1.w};
            float bv[8] = {b0.x, b0.y, b0.z, b0.w, b1.x, b1.y, b1.z, b1.w};
#pragma unroll
            for (int i = 0; i < 8; i++)
#pragma unroll
                for (int j = 0; j < 8; j++) acc[i][j] += av[i] * bv[j];
        }
        __syncthreads();
    }
#pragma unroll
    for (int j = 0; j < 8; j++) {
        int col = col0 + tx * 8 + j;
        float bias = bmix[col] + bskip[col];
#pragma unroll
        for (int i = 0; i < 8; i++)
            out[(size_t)(row0 + ty * 8 + i) * DOUT + col] = acc[i][j] + bias;
    }
}

// ---------------------------------------------------------------------------
// Launch
// ---------------------------------------------------------------------------
extern "C" void kernel_launch(void* const* d_in, const int* in_sizes, int n_in,
                              void* d_out, int out_size) {
    const float* x     = (const float*)d_in[0];
    const float* s_re  = (const float*)d_in[1];
    const float* s_im  = (const float*)d_in[2];
    const int*   start = (const int*)d_in[3];   // nonzero test: works for int32 or f32 0/1
    // d_in[4] = next_done (unused by reference)
    const float* Wpre  = (const float*)d_in[5];
    const float* bpre  = (const float*)d_in[6];
    const float* Wskip = (const float*)d_in[7];
    const float* bskip = (const float*)d_in[8];
    const float* Wmix  = (const float*)d_in[9];
    const float* bmix  = (const float*)d_in[10];
    const float* a     = (const float*)d_in[11];
    const float* bf    = (const float*)d_in[12];
    float* out = (float*)d_out;
    // Output 1 (final complex state) is serialized PLANAR: 1024 reals then
    // 1024 imags, starting right after output 0's 8192*1024 floats.
    float* stateOut = out + (size_t)TT * DOUT;

    k_pre<<<TT / 64, 256>>>(x, Wpre, bpre);
    k_chunk<<<NCHUNK, 256>>>(start, a, bf);
    k_chain<<<1, NCH>>>(s_re, s_im, a, bf, stateOut);
    k_emit<<<NCHUNK, 256>>>(start, a, bf);
    dim3 g3(DOUT / BN, TT / BM);
    k_out<<<g3, 256>>>(x, Wmix, bmix, Wskip, bskip, out);
}

// round 5
// speedup vs baseline: 1.7157x; 1.7157x over previous
#include <cuda_runtime.h>
#include <cuda_bf16.h>
#include <math.h>
#include <stdint.h>

// ---------------------------------------------------------------------------
// SFFM: pre-GEMM + rownorm -> resettable complex scan -> mix/skip GEMM
// ---------------------------------------------------------------------------
#define TT      8192
#define DIN     1024
#define DOUT    1024
#define MTR     64
#define CCT     16
#define NCH     1024
#define CHUNK   64
#define NCHUNK  128
#define DMIX    2048
#define KTOT    (DMIX + DIN)  // 3072

// Scratch
__device__ float g_pre[TT * MTR];
__device__ float g_Bre[NCHUNK * NCH];
__device__ float g_Bim[NCHUNK * NCH];
__device__ float g_cRe[NCHUNK * NCH];
__device__ float g_cIm[NCHUNK * NCH];
__device__ int   g_any[NCHUNK];
__device__ float g_zin[TT * DMIX];

// ---------------------------------------------------------------------------
// K1: pre = rownorm(x @ W_pre^T + b_pre)
// ---------------------------------------------------------------------------
__global__ __launch_bounds__(256) void k_pre(const float* __restrict__ x,
                                             const float* __restrict__ Wp,
                                             const float* __restrict__ bp) {
    __shared__ float xs[32][65];
    __shared__ float ws[32][65];
    __shared__ float nrm[64];
    const int tid = threadIdx.x;
    const int ty = tid >> 4, tx = tid & 15;
    const int row0 = blockIdx.x * 64;

    float acc[4][4];
#pragma unroll
    for (int i = 0; i < 4; i++)
#pragma unroll
        for (int j = 0; j < 4; j++) acc[i][j] = 0.f;

    for (int k0 = 0; k0 < DIN; k0 += 32) {
#pragma unroll
        for (int r = 0; r < 8; r++) {
            int idx = tid + r * 256;
            int m = idx >> 5, k = idx & 31;
            xs[k][m] = x[(size_t)(row0 + m) * DIN + k0 + k];
            ws[k][m] = Wp[(size_t)m * DIN + k0 + k];
        }
        __syncthreads();
#pragma unroll
        for (int kk = 0; kk < 32; kk++) {
            float av[4], bv[4];
#pragma unroll
            for (int i = 0; i < 4; i++) av[i] = xs[kk][ty * 4 + i];
#pragma unroll
            for (int j = 0; j < 4; j++) bv[j] = ws[kk][tx * 4 + j];
#pragma unroll
            for (int i = 0; i < 4; i++)
#pragma unroll
                for (int j = 0; j < 4; j++) acc[i][j] += av[i] * bv[j];
        }
        __syncthreads();
    }
#pragma unroll
    for (int j = 0; j < 4; j++) {
        float b = bp[tx * 4 + j];
#pragma unroll
        for (int i = 0; i < 4; i++) acc[i][j] += b;
    }
    if (tid < 64) nrm[tid] = 0.f;
    __syncthreads();
#pragma unroll
    for (int i = 0; i < 4; i++) {
        float s = 0.f;
#pragma unroll
        for (int j = 0; j < 4; j++) s += acc[i][j] * acc[i][j];
        atomicAdd(&nrm[ty * 4 + i], s);
    }
    __syncthreads();
#pragma unroll
    for (int i = 0; i < 4; i++) {
        float inv = 1.0f / (1e-6f + sqrtf(nrm[ty * 4 + i]));
#pragma unroll
        for (int j = 0; j < 4; j++)
            g_pre[(size_t)(row0 + ty * 4 + i) * MTR + tx * 4 + j] = acc[i][j] * inv;
    }
}

// ---------------------------------------------------------------------------
// K2a: per-chunk local scan from S=0 -> transfer (B, anyStart)
// ---------------------------------------------------------------------------
__global__ __launch_bounds__(256) void k_chunk(const int* __restrict__ start,
                                               const float* __restrict__ a,
                                               const float* __restrict__ bfreq) {
    __shared__ float sp[CHUNK][MTR];
    __shared__ int ss[CHUNK];
    __shared__ int sAny;
    const int tid = threadIdx.x;
    const int ck = blockIdx.x;
    const int t0 = ck * CHUNK;

    for (int idx = tid; idx < CHUNK * MTR; idx += 256)
        sp[idx >> 6][idx & 63] = g_pre[(size_t)(t0 + (idx >> 6)) * MTR + (idx & 63)];
    if (tid < CHUNK) ss[tid] = (start[t0 + tid] != 0);
    if (tid == 0) sAny = 0;
    __syncthreads();
    if (tid < CHUNK && ss[tid]) atomicOr(&sAny, 1);

    const int m = tid >> 2;
    const float gmag = expf(-fabsf(a[m]));
    float gre[4], gim[4], Sre[4], Sim[4];
#pragma unroll
    for (int q = 0; q < 4; q++) {
        int c = ((tid & 3) << 2) + q;
        float sv, cv; sincosf(bfreq[c], &sv, &cv);
        gre[q] = gmag * cv; gim[q] = gmag * sv;
        Sre[q] = 0.f; Sim[q] = 0.f;
    }
    for (int t = 0; t < CHUNK; t++) {
        float p = sp[t][m];
        float keep = ss[t] ? 0.f : 1.f;
#pragma unroll
        for (int q = 0; q < 4; q++) {
            float r  = keep * (gre[q] * Sre[q] - gim[q] * Sim[q]) + p;
            float im = keep * (gre[q] * Sim[q] + gim[q] * Sre[q]);
            Sre[q] = r; Sim[q] = im;
        }
    }
#pragma unroll
    for (int q = 0; q < 4; q++) {
        int ch = tid * 4 + q;
        g_Bre[(size_t)ck * NCH + ch] = Sre[q];
        g_Bim[(size_t)ck * NCH + ch] = Sim[q];
    }
    __syncthreads();
    if (tid == 0) g_any[ck] = sAny;
}

// ---------------------------------------------------------------------------
// K2b: sequential chain over chunks + final carry state (PLANAR re/im)
// ---------------------------------------------------------------------------
__global__ __launch_bounds__(1024) void k_chain(const float* __restrict__ s_re0,
                                                const float* __restrict__ s_im0,
                                                const float* __restrict__ a,
                                                const float* __restrict__ bfreq,
                                                float* stateOut) {
    const int ch = threadIdx.x;
    const int m = ch >> 4, c = ch & 15;
    const float Amag = expf(-64.f * fabsf(a[m]));
    float sv, cv; sincosf(64.f * bfreq[c], &sv, &cv);
    const float Are = Amag * cv, Aim = Amag * sv;
    float Sre = s_re0[ch], Sim = s_im0[ch];
#pragma unroll 4
    for (int k = 0; k < NCHUNK; k++) {
        g_cRe[(size_t)k * NCH + ch] = Sre;
        g_cIm[(size_t)k * NCH + ch] = Sim;
        float br = g_Bre[(size_t)k * NCH + ch];
        float bi = g_Bim[(size_t)k * NCH + ch];
        float keep = g_any[k] ? 0.f : 1.f;
        float r  = keep * (Are * Sre - Aim * Sim) + br;
        float im = keep * (Are * Sim + Aim * Sre) + bi;
        Sre = r; Sim = im;
    }
    stateOut[ch]       = Sre;
    stateOut[NCH + ch] = Sim;
}

// ---------------------------------------------------------------------------
// K2c: re-scan with true carry, emit z_in [T,2048]
// ---------------------------------------------------------------------------
__global__ __launch_bounds__(256) void k_emit(const int* __restrict__ start,
                                              const float* __restrict__ a,
                                              const float* __restrict__ bfreq) {
    __shared__ float sp[CHUNK][MTR];
    __shared__ int ss[CHUNK];
    const int tid = threadIdx.x;
    const int ck = blockIdx.x;
    const int t0 = ck * CHUNK;

    for (int idx = tid; idx < CHUNK * MTR; idx += 256)
        sp[idx >> 6][idx & 63] = g_pre[(size_t)(t0 + (idx >> 6)) * MTR + (idx & 63)];
    if (tid < CHUNK) ss[tid] = (start[t0 + tid] != 0);
    __syncthreads();

    const int m = tid >> 2;
    const float gmag = expf(-fabsf(a[m]));
    float gre[4], gim[4], Sre[4], Sim[4];
    int cidx[4];
#pragma unroll
    for (int q = 0; q < 4; q++) {
        int c = ((tid & 3) << 2) + q;
        cidx[q] = c;
        float sv, cv; sincosf(bfreq[c], &sv, &cv);
        gre[q] = gmag * cv; gim[q] = gmag * sv;
        int ch = tid * 4 + q;
        Sre[q] = g_cRe[(size_t)ck * NCH + ch];
        Sim[q] = g_cIm[(size_t)ck * NCH + ch];
    }
    for (int t = 0; t < CHUNK; t++) {
        float p = sp[t][m];
        float keep = ss[t] ? 0.f : 1.f;
        size_t rowbase = (size_t)(t0 + t) * DMIX + (size_t)m * 32;
#pragma unroll
        for (int q = 0; q < 4; q++) {
            float r  = keep * (gre[q] * Sre[q] - gim[q] * Sim[q]) + p;
            float im = keep * (gre[q] * Sim[q] + gim[q] * Sre[q]);
            Sre[q] = r; Sim[q] = im;
            g_zin[rowbase + cidx[q]]      = r;
            g_zin[rowbase + 16 + cidx[q]] = im;
        }
    }
}

// ---------------------------------------------------------------------------
// mma.sync helpers (sm_80+ path; tcgen05 is unavailable: ptxas target = sm_100)
// ---------------------------------------------------------------------------
__device__ __forceinline__ void ldsm4(uint32_t* r, uint32_t addr) {
    asm volatile("ldmatrix.sync.aligned.m8n8.x4.shared.b16 {%0,%1,%2,%3}, [%4];"
                 : "=r"(r[0]), "=r"(r[1]), "=r"(r[2]), "=r"(r[3]) : "r"(addr));
}
__device__ __forceinline__ void mma_bf16(float* d, const uint32_t* a, const uint32_t* b) {
    asm volatile("mma.sync.aligned.m16n8k16.row.col.f32.bf16.bf16.f32 "
                 "{%0,%1,%2,%3}, {%4,%5,%6,%7}, {%8,%9}, {%0,%1,%2,%3};"
                 : "+f"(d[0]), "+f"(d[1]), "+f"(d[2]), "+f"(d[3])
                 : "r"(a[0]), "r"(a[1]), "r"(a[2]), "r"(a[3]), "r"(b[0]), "r"(b[1]));
}
__device__ __forceinline__ uint32_t smem_u32(const void* p) {
    uint32_t a;
    asm("{ .reg .u64 t; cvta.to.shared.u64 t, %1; cvt.u32.u64 %0, t; }" : "=r"(a) : "l"(p));
    return a;
}
// split fp32 -> bf16 hi + bf16 lo (residual), packed as bf16x2 words
__device__ __forceinline__ void split2(float xx, float yy, uint32_t& hi, uint32_t& lo) {
    __nv_bfloat16 hx = __float2bfloat16_rn(xx), hy = __float2bfloat16_rn(yy);
    float rx = xx - __bfloat162float(hx);
    float ry = yy - __bfloat162float(hy);
    __nv_bfloat16 lx = __float2bfloat16_rn(rx), ly = __float2bfloat16_rn(ry);
    hi = (uint32_t)__bfloat16_as_ushort(hx) | ((uint32_t)__bfloat16_as_ushort(hy) << 16);
    lo = (uint32_t)__bfloat16_as_ushort(lx) | ((uint32_t)__bfloat16_as_ushort(ly) << 16);
}

// ---------------------------------------------------------------------------
// K3: out = z_in @ Wmix^T + x @ Wskip^T + biases, bf16-split mma.sync.
// CTA 128x128, BK=32, 8 warps (2m x 4n), warp tile 64x32.
// Smem rows padded to 80B (20 banks) -> conflict-free ldmatrix.
// Accumulate Ahi*Bhi + Ahi*Blo + Alo*Bhi in fp32 (err ~1e-5).
// ---------------------------------------------------------------------------
#define ROWB     80                       // padded row stride (bytes) for 32 bf16
#define OFF_AHI  0
#define OFF_ALO  10240
#define OFF_BHI  20480
#define OFF_BLO  30720
#define STG_SZ   40960
#define SM_TOTAL (1024 + 2 * STG_SZ)      // 82944
#define KTILES   (KTOT / 32)              // 96
#define MIXTILES (DMIX / 32)              // 64

__global__ __launch_bounds__(256) void k_out_mma(const float* __restrict__ x,
                                                 const float* __restrict__ Wmix,
                                                 const float* __restrict__ bmix,
                                                 const float* __restrict__ Wskip,
                                                 const float* __restrict__ bskip,
                                                 float* __restrict__ out) {
    extern __shared__ char smem[];
    float* bias_s = (float*)smem;
    const uint32_t sb = smem_u32(smem);
    const int tid = threadIdx.x;
    const int lane = tid & 31, wid = tid >> 5;
    const int warp_m = wid & 1, warp_n = wid >> 1;
    const int row0 = blockIdx.y * 128;
    const int col0 = blockIdx.x * 128;

    if (tid < 128) bias_s[tid] = bmix[col0 + tid] + bskip[col0 + tid];

    float acc[4][4][4];
#pragma unroll
    for (int i = 0; i < 4; i++)
#pragma unroll
        for (int j = 0; j < 4; j++)
#pragma unroll
            for (int q = 0; q < 4; q++) acc[i][j][q] = 0.f;

    // per-thread global-load geometry: 4 float4 each for A and B per tile
    const int lrw = tid >> 1;             // unused fallback; real mapping below
    (void)lrw;

    float4 ra[4], rb[4];

    // --- tile loader (LDG into regs) ---
    auto ldg_tile = [&](int kt) {
        const bool mixPart = kt < MIXTILES;
        const float* sA = mixPart ? g_zin : x;
        const float* sB = mixPart ? Wmix : Wskip;
        const int ldx = mixPart ? DMIX : DIN;
        const int kk0 = mixPart ? kt * 32 : (kt - MIXTILES) * 32;
#pragma unroll
        for (int r = 0; r < 4; r++) {
            int idx = tid + r * 256;      // 0..1023
            int rw = idx >> 3;
            int kq = (idx & 7) << 2;
            ra[r] = *(const float4*)(sA + (size_t)(row0 + rw) * ldx + kk0 + kq);
            rb[r] = *(const float4*)(sB + (size_t)(col0 + rw) * ldx + kk0 + kq);
        }
    };
    // --- split + store to a stage ---
    auto sts_tile = [&](char* stgp) {
#pragma unroll
        for (int r = 0; r < 4; r++) {
            int idx = tid + r * 256;
            int rw = idx >> 3;
            int kq = (idx & 7) << 2;
            uint32_t off = (uint32_t)rw * ROWB + kq * 2;
            uint32_t h0, l0, h1, l1;
            split2(ra[r].x, ra[r].y, h0, l0);
            split2(ra[r].z, ra[r].w, h1, l1);
            *(uint2*)(stgp + OFF_AHI + off) = make_uint2(h0, h1);
            *(uint2*)(stgp + OFF_ALO + off) = make_uint2(l0, l1);
            split2(rb[r].x, rb[r].y, h0, l0);
            split2(rb[r].z, rb[r].w, h1, l1);
            *(uint2*)(stgp + OFF_BHI + off) = make_uint2(h0, h1);
            *(uint2*)(stgp + OFF_BLO + off) = make_uint2(l0, l1);
        }
    };

    // preload tile 0 into stage 0
    ldg_tile(0);
    sts_tile(smem + 1024);
    __syncthreads();

    // ldmatrix per-lane base offsets (within a stage)
    const uint32_t aoff = (uint32_t)(warp_m * 64 + (lane & 15)) * ROWB
                        + ((lane >> 4) & 1) * 16;
    const uint32_t boff = (uint32_t)(warp_n * 32 + (lane & 7) + (((lane >> 4) & 1) << 3)) * ROWB
                        + ((lane >> 3) & 1) * 16;

    for (int kt = 0; kt < KTILES; kt++) {
        const uint32_t stg = sb + 1024 + (uint32_t)(kt & 1) * STG_SZ;
        const bool pf = (kt + 1 < KTILES);
        if (pf) ldg_tile(kt + 1);

#pragma unroll
        for (int s = 0; s < 2; s++) {
            const uint32_t ks = s * 32;   // byte offset of k16 half
            uint32_t bh[8], bl[8], afr[16];
            ldsm4(bh + 0, stg + OFF_BHI + boff + ks);
            ldsm4(bh + 4, stg + OFF_BHI + boff + 16 * ROWB + ks);
            ldsm4(bl + 0, stg + OFF_BLO + boff + ks);
            ldsm4(bl + 4, stg + OFF_BLO + boff + 16 * ROWB + ks);
#pragma unroll
            for (int i = 0; i < 4; i++)
                ldsm4(afr + i * 4, stg + OFF_AHI + aoff + (uint32_t)i * 16 * ROWB + ks);
#pragma unroll
            for (int i = 0; i < 4; i++)
#pragma unroll
                for (int j = 0; j < 4; j++)
                    mma_bf16(acc[i][j], afr + i * 4, bh + j * 2);
#pragma unroll
            for (int i = 0; i < 4; i++)
#pragma unroll
                for (int j = 0; j < 4; j++)
                    mma_bf16(acc[i][j], afr + i * 4, bl + j * 2);
#pragma unroll
            for (int i = 0; i < 4; i++)
                ldsm4(afr + i * 4, stg + OFF_ALO + aoff + (uint32_t)i * 16 * ROWB + ks);
#pragma unroll
            for (int i = 0; i < 4; i++)
#pragma unroll
                for (int j = 0; j < 4; j++)
                    mma_bf16(acc[i][j], afr + i * 4, bh + j * 2);
        }

        if (pf) sts_tile(smem + 1024 + ((kt + 1) & 1) * STG_SZ);
        __syncthreads();
    }

    // epilogue: D frag (m16n8): d0=(r, c), d1=(r, c+1), d2=(r+8, c), d3=(r+8, c+1)
    const int r_base = row0 + warp_m * 64 + (lane >> 2);
    const int c_base = warp_n * 32 + (lane & 3) * 2;   // relative to col0
#pragma unroll
    for (int i = 0; i < 4; i++) {
#pragma unroll
        for (int j = 0; j < 4; j++) {
            int r = r_base + i * 16;
            int c = c_base + j * 8;
            float b0 = bias_s[c], b1 = bias_s[c + 1];
            float2 v0 = make_float2(acc[i][j][0] + b0, acc[i][j][1] + b1);
            float2 v1 = make_float2(acc[i][j][2] + b0, acc[i][j][3] + b1);
            *(float2*)(out + (size_t)r * DOUT + col0 + c) = v0;
            *(float2*)(out + (size_t)(r + 8) * DOUT + col0 + c) = v1;
        }
    }
}

// ---------------------------------------------------------------------------
// Launch
// ---------------------------------------------------------------------------
extern "C" void kernel_launch(void* const* d_in, const int* in_sizes, int n_in,
                              void* d_out, int out_size) {
    const float* x     = (const float*)d_in[0];
    const float* s_re  = (const float*)d_in[1];
    const float* s_im  = (const float*)d_in[2];
    const int*   start = (const int*)d_in[3];
    const float* Wpre  = (const float*)d_in[5];
    const float* bpre  = (const float*)d_in[6];
    const float* Wskip = (const float*)d_in[7];
    const float* bskip = (const float*)d_in[8];
    const float* Wmix  = (const float*)d_in[9];
    const float* bmix  = (const float*)d_in[10];
    const float* a     = (const float*)d_in[11];
    const float* bf    = (const float*)d_in[12];
    float* out = (float*)d_out;
    float* stateOut = out + (size_t)TT * DOUT;  // planar: 1024 re then 1024 im

    cudaFuncSetAttribute(k_out_mma, cudaFuncAttributeMaxDynamicSharedMemorySize, SM_TOTAL);

    k_pre<<<TT / 64, 256>>>(x, Wpre, bpre);
    k_chunk<<<NCHUNK, 256>>>(start, a, bf);
    k_chain<<<1, NCH>>>(s_re, s_im, a, bf, stateOut);
    k_emit<<<NCHUNK, 256>>>(start, a, bf);
    dim3 g3(DOUT / 128, TT / 128);   // x = N-block (fast) for L2 reuse of A rows
    k_out_mma<<<g3, 256, SM_TOTAL>>>(x, Wmix, bmix, Wskip, bskip, out);
}

// round 6
// speedup vs baseline: 2.2424x; 1.3070x over previous
#include <cuda_runtime.h>
#include <cuda_bf16.h>
#include <math.h>
#include <stdint.h>

#define TT      8192
#define DIN     1024
#define DOUT    1024
#define MTR     64
#define CCT     16
#define NCH     1024
#define CHUNK   64
#define NCHUNK  128
#define DMIX    2048
#define KTOT    (DMIX + DIN)  // 3072

// Scratch
__device__ float g_pre[TT * MTR];
__device__ float g_Bre[NCHUNK * NCH];
__device__ float g_Bim[NCHUNK * NCH];
__device__ float g_cRe[NCHUNK * NCH];
__device__ float g_cIm[NCHUNK * NCH];
__device__ int   g_any[NCHUNK];
// bf16 hi/lo planes for the big GEMM
__device__ __nv_bfloat16 g_zinH[TT * DMIX];
__device__ __nv_bfloat16 g_zinL[TT * DMIX];
__device__ __nv_bfloat16 g_xH[TT * DIN];
__device__ __nv_bfloat16 g_xL[TT * DIN];
__device__ __nv_bfloat16 g_wmH[DOUT * DMIX];
__device__ __nv_bfloat16 g_wmL[DOUT * DMIX];
__device__ __nv_bfloat16 g_wsH[DOUT * DIN];
__device__ __nv_bfloat16 g_wsL[DOUT * DIN];

// ---------------------------------------------------------------------------
// helpers
// ---------------------------------------------------------------------------
__device__ __forceinline__ uint32_t smem_u32(const void* p) {
    uint32_t a;
    asm("{ .reg .u64 t; cvta.to.shared.u64 t, %1; cvt.u32.u64 %0, t; }" : "=r"(a) : "l"(p));
    return a;
}
__device__ __forceinline__ void ldsm4(uint32_t* r, uint32_t addr) {
    asm volatile("ldmatrix.sync.aligned.m8n8.x4.shared.b16 {%0,%1,%2,%3}, [%4];"
                 : "=r"(r[0]), "=r"(r[1]), "=r"(r[2]), "=r"(r[3]) : "r"(addr));
}
__device__ __forceinline__ void mma_bf16(float* d, const uint32_t* a, const uint32_t* b) {
    asm volatile("mma.sync.aligned.m16n8k16.row.col.f32.bf16.bf16.f32 "
                 "{%0,%1,%2,%3}, {%4,%5,%6,%7}, {%8,%9}, {%0,%1,%2,%3};"
                 : "+f"(d[0]), "+f"(d[1]), "+f"(d[2]), "+f"(d[3])
                 : "r"(a[0]), "r"(a[1]), "r"(a[2]), "r"(a[3]), "r"(b[0]), "r"(b[1]));
}
__device__ __forceinline__ void cp16(uint32_t dst, const void* src) {
    asm volatile("cp.async.cg.shared.global [%0], [%1], 16;"
                 :: "r"(dst), "l"(src) : "memory");
}
#define CP_COMMIT() asm volatile("cp.async.commit_group;" ::: "memory")
#define CP_WAIT(n)  asm volatile("cp.async.wait_group %0;" :: "n"(n) : "memory")

// fp32 -> (bf16 hi, bf16 lo residual)
__device__ __forceinline__ void splitbf(float v, __nv_bfloat16& h, __nv_bfloat16& l) {
    h = __float2bfloat16_rn(v);
    l = __float2bfloat16_rn(v - __bfloat162float(h));
}
__device__ __forceinline__ uint32_t pack2(__nv_bfloat16 a, __nv_bfloat16 b) {
    return (uint32_t)__bfloat16_as_ushort(a) | ((uint32_t)__bfloat16_as_ushort(b) << 16);
}

// ---------------------------------------------------------------------------
// K0: fused splitter for x, Wmix, Wskip -> bf16 hi/lo planes
// ---------------------------------------------------------------------------
#define N4_X   (TT * DIN / 4)       // 2M
#define N4_WM  (DOUT * DMIX / 4)    // 512K
#define N4_WS  (DOUT * DIN / 4)     // 256K
#define N4_ALL (N4_X + N4_WM + N4_WS)

__global__ __launch_bounds__(256) void k_split(const float* __restrict__ x,
                                               const float* __restrict__ Wmix,
                                               const float* __restrict__ Wskip) {
    int i = blockIdx.x * blockDim.x + threadIdx.x;
    if (i >= N4_ALL) return;
    const float* src; __nv_bfloat16 *dH, *dL; int j;
    if (i < N4_X)              { src = x;     dH = g_xH;  dL = g_xL;  j = i; }
    else if (i < N4_X + N4_WM) { src = Wmix;  dH = g_wmH; dL = g_wmL; j = i - N4_X; }
    else                       { src = Wskip; dH = g_wsH; dL = g_wsL; j = i - N4_X - N4_WM; }
    float4 v = ((const float4*)src)[j];
    __nv_bfloat16 h0, l0, h1, l1, h2, l2, h3, l3;
    splitbf(v.x, h0, l0); splitbf(v.y, h1, l1);
    splitbf(v.z, h2, l2); splitbf(v.w, h3, l3);
    ((uint2*)dH)[j] = make_uint2(pack2(h0, h1), pack2(h2, h3));
    ((uint2*)dL)[j] = make_uint2(pack2(l0, l1), pack2(l2, l3));
}

// ---------------------------------------------------------------------------
// K1: pre = rownorm(x @ W_pre^T + b_pre)
// ---------------------------------------------------------------------------
__global__ __launch_bounds__(256) void k_pre(const float* __restrict__ x,
                                             const float* __restrict__ Wp,
                                             const float* __restrict__ bp) {
    __shared__ float xs[32][65];
    __shared__ float ws[32][65];
    __shared__ float nrm[64];
    const int tid = threadIdx.x;
    const int ty = tid >> 4, tx = tid & 15;
    const int row0 = blockIdx.x * 64;

    float acc[4][4];
#pragma unroll
    for (int i = 0; i < 4; i++)
#pragma unroll
        for (int j = 0; j < 4; j++) acc[i][j] = 0.f;

    for (int k0 = 0; k0 < DIN; k0 += 32) {
#pragma unroll
        for (int r = 0; r < 8; r++) {
            int idx = tid + r * 256;
            int m = idx >> 5, k = idx & 31;
            xs[k][m] = x[(size_t)(row0 + m) * DIN + k0 + k];
            ws[k][m] = Wp[(size_t)m * DIN + k0 + k];
        }
        __syncthreads();
#pragma unroll
        for (int kk = 0; kk < 32; kk++) {
            float av[4], bv[4];
#pragma unroll
            for (int i = 0; i < 4; i++) av[i] = xs[kk][ty * 4 + i];
#pragma unroll
            for (int j = 0; j < 4; j++) bv[j] = ws[kk][tx * 4 + j];
#pragma unroll
            for (int i = 0; i < 4; i++)
#pragma unroll
                for (int j = 0; j < 4; j++) acc[i][j] += av[i] * bv[j];
        }
        __syncthreads();
    }
#pragma unroll
    for (int j = 0; j < 4; j++) {
        float b = bp[tx * 4 + j];
#pragma unroll
        for (int i = 0; i < 4; i++) acc[i][j] += b;
    }
    if (tid < 64) nrm[tid] = 0.f;
    __syncthreads();
#pragma unroll
    for (int i = 0; i < 4; i++) {
        float s = 0.f;
#pragma unroll
        for (int j = 0; j < 4; j++) s += acc[i][j] * acc[i][j];
        atomicAdd(&nrm[ty * 4 + i], s);
    }
    __syncthreads();
#pragma unroll
    for (int i = 0; i < 4; i++) {
        float inv = 1.0f / (1e-6f + sqrtf(nrm[ty * 4 + i]));
#pragma unroll
        for (int j = 0; j < 4; j++)
            g_pre[(size_t)(row0 + ty * 4 + i) * MTR + tx * 4 + j] = acc[i][j] * inv;
    }
}

// ---------------------------------------------------------------------------
// K2a: per-chunk local scan from S=0 -> transfer (B, anyStart)
// ---------------------------------------------------------------------------
__global__ __launch_bounds__(256) void k_chunk(const int* __restrict__ start,
                                               const float* __restrict__ a,
                                               const float* __restrict__ bfreq) {
    __shared__ float sp[CHUNK][MTR];
    __shared__ int ss[CHUNK];
    __shared__ int sAny;
    const int tid = threadIdx.x;
    const int ck = blockIdx.x;
    const int t0 = ck * CHUNK;

    for (int idx = tid; idx < CHUNK * MTR; idx += 256)
        sp[idx >> 6][idx & 63] = g_pre[(size_t)(t0 + (idx >> 6)) * MTR + (idx & 63)];
    if (tid < CHUNK) ss[tid] = (start[t0 + tid] != 0);
    if (tid == 0) sAny = 0;
    __syncthreads();
    if (tid < CHUNK && ss[tid]) atomicOr(&sAny, 1);

    const int m = tid >> 2;
    const float gmag = expf(-fabsf(a[m]));
    float gre[4], gim[4], Sre[4], Sim[4];
#pragma unroll
    for (int q = 0; q < 4; q++) {
        int c = ((tid & 3) << 2) + q;
        float sv, cv; sincosf(bfreq[c], &sv, &cv);
        gre[q] = gmag * cv; gim[q] = gmag * sv;
        Sre[q] = 0.f; Sim[q] = 0.f;
    }
    for (int t = 0; t < CHUNK; t++) {
        float p = sp[t][m];
        float keep = ss[t] ? 0.f : 1.f;
#pragma unroll
        for (int q = 0; q < 4; q++) {
            float r  = keep * (gre[q] * Sre[q] - gim[q] * Sim[q]) + p;
            float im = keep * (gre[q] * Sim[q] + gim[q] * Sre[q]);
            Sre[q] = r; Sim[q] = im;
        }
    }
#pragma unroll
    for (int q = 0; q < 4; q++) {
        int ch = tid * 4 + q;
        g_Bre[(size_t)ck * NCH + ch] = Sre[q];
        g_Bim[(size_t)ck * NCH + ch] = Sim[q];
    }
    __syncthreads();
    if (tid == 0) g_any[ck] = sAny;
}

// ---------------------------------------------------------------------------
// K2b: sequential chain over chunks + final carry state (PLANAR re/im)
// ---------------------------------------------------------------------------
__global__ __launch_bounds__(1024) void k_chain(const float* __restrict__ s_re0,
                                                const float* __restrict__ s_im0,
                                                const float* __restrict__ a,
                                                const float* __restrict__ bfreq,
                                                float* stateOut) {
    const int ch = threadIdx.x;
    const int m = ch >> 4, c = ch & 15;
    const float Amag = expf(-64.f * fabsf(a[m]));
    float sv, cv; sincosf(64.f * bfreq[c], &sv, &cv);
    const float Are = Amag * cv, Aim = Amag * sv;
    float Sre = s_re0[ch], Sim = s_im0[ch];
#pragma unroll 4
    for (int k = 0; k < NCHUNK; k++) {
        g_cRe[(size_t)k * NCH + ch] = Sre;
        g_cIm[(size_t)k * NCH + ch] = Sim;
        float br = g_Bre[(size_t)k * NCH + ch];
        float bi = g_Bim[(size_t)k * NCH + ch];
        float keep = g_any[k] ? 0.f : 1.f;
        float r  = keep * (Are * Sre - Aim * Sim) + br;
        float im = keep * (Are * Sim + Aim * Sre) + bi;
        Sre = r; Sim = im;
    }
    stateOut[ch]       = Sre;
    stateOut[NCH + ch] = Sim;
}

// ---------------------------------------------------------------------------
// K2c: re-scan with true carry, emit zin directly as bf16 hi/lo planes.
// Thread handles m = tid>>2, c = (tid&3)*4 + q (4 consecutive c's) so the 4
// Re (and 4 Im) bf16 values form one 8-byte store per plane.
// ---------------------------------------------------------------------------
__global__ __launch_bounds__(256) void k_emit(const int* __restrict__ start,
                                              const float* __restrict__ a,
                                              const float* __restrict__ bfreq) {
    __shared__ float sp[CHUNK][MTR];
    __shared__ int ss[CHUNK];
    const int tid = threadIdx.x;
    const int ck = blockIdx.x;
    const int t0 = ck * CHUNK;

    for (int idx = tid; idx < CHUNK * MTR; idx += 256)
        sp[idx >> 6][idx & 63] = g_pre[(size_t)(t0 + (idx >> 6)) * MTR + (idx & 63)];
    if (tid < CHUNK) ss[tid] = (start[t0 + tid] != 0);
    __syncthreads();

    const int m = tid >> 2;
    const int cg = tid & 3;
    const float gmag = expf(-fabsf(a[m]));
    float gre[4], gim[4], Sre[4], Sim[4];
#pragma unroll
    for (int q = 0; q < 4; q++) {
        int c = cg * 4 + q;
        float sv, cv; sincosf(bfreq[c], &sv, &cv);
        gre[q] = gmag * cv; gim[q] = gmag * sv;
        int ch = m * CCT + c;
        Sre[q] = g_cRe[(size_t)ck * NCH + ch];
        Sim[q] = g_cIm[(size_t)ck * NCH + ch];
    }
    for (int t = 0; t < CHUNK; t++) {
        float p = sp[t][m];
        float keep = ss[t] ? 0.f : 1.f;
#pragma unroll
        for (int q = 0; q < 4; q++) {
            float r  = keep * (gre[q] * Sre[q] - gim[q] * Sim[q]) + p;
            float im = keep * (gre[q] * Sim[q] + gim[q] * Sre[q]);
            Sre[q] = r; Sim[q] = im;
        }
        size_t base = (size_t)(t0 + t) * DMIX + (size_t)m * 32 + cg * 4;
        __nv_bfloat16 h[8], l[8];
#pragma unroll
        for (int q = 0; q < 4; q++) { splitbf(Sre[q], h[q], l[q]); }
#pragma unroll
        for (int q = 0; q < 4; q++) { splitbf(Sim[q], h[4 + q], l[4 + q]); }
        *(uint2*)(g_zinH + base)      = make_uint2(pack2(h[0], h[1]), pack2(h[2], h[3]));
        *(uint2*)(g_zinH + base + 16) = make_uint2(pack2(h[4], h[5]), pack2(h[6], h[7]));
        *(uint2*)(g_zinL + base)      = make_uint2(pack2(l[0], l[1]), pack2(l[2], l[3]));
        *(uint2*)(g_zinL + base + 16) = make_uint2(pack2(l[4], l[5]), pack2(l[6], l[7]));
    }
}

// ---------------------------------------------------------------------------
// K3: out = z_in @ Wmix^T + x @ Wskip^T + biases.
// Pure bf16 operands (preconverted hi/lo planes), cp.async double buffer,
// CTA 128x128, BK=32, 8 warps (2m x 4n), 2 CTAs/SM.
// ---------------------------------------------------------------------------
#define ROWB     80                       // padded row stride for 32 bf16 (64B) rows
#define OFF_AHI  0
#define OFF_ALO  10240
#define OFF_BHI  20480
#define OFF_BLO  30720
#define STG_SZ   40960
#define SM_TOTAL (1024 + 2 * STG_SZ)      // 82944
#define KTILES   (KTOT / 32)              // 96
#define MIXTILES (DMIX / 32)              // 64

__global__ __launch_bounds__(256, 2) void k_out_mma(const float* __restrict__ bmix,
                                                    const float* __restrict__ bskip,
                                                    float* __restrict__ out) {
    extern __shared__ char smem[];
    float* bias_s = (float*)smem;
    const uint32_t sb = smem_u32(smem);
    const int tid = threadIdx.x;
    const int lane = tid & 31, wid = tid >> 5;
    const int warp_m = wid & 1, warp_n = wid >> 1;
    const int row0 = blockIdx.y * 128;
    const int col0 = blockIdx.x * 128;

    if (tid < 128) bias_s[tid] = bmix[col0 + tid] + bskip[col0 + tid];

    float acc[4][4][4];
#pragma unroll
    for (int i = 0; i < 4; i++)
#pragma unroll
        for (int j = 0; j < 4; j++)
#pragma unroll
            for (int q = 0; q < 4; q++) acc[i][j][q] = 0.f;

    // cp.async tile issuance: 8 x 16B per thread (2 per array)
    auto issue_cp = [&](int kt, uint32_t stg) {
        const bool mix = kt < MIXTILES;
        const __nv_bfloat16* aH = mix ? g_zinH : g_xH;
        const __nv_bfloat16* aL = mix ? g_zinL : g_xL;
        const __nv_bfloat16* bH = mix ? g_wmH : g_wsH;
        const __nv_bfloat16* bL = mix ? g_wmL : g_wsL;
        const int ldx = mix ? DMIX : DIN;
        const int kk0 = mix ? kt * 32 : (kt - MIXTILES) * 32;
#pragma unroll
        for (int r = 0; r < 2; r++) {
            int ci = tid + r * 256;            // 0..511 chunks (128 rows x 4)
            int rw = ci >> 2, c16 = ci & 3;
            uint32_t soff = (uint32_t)rw * ROWB + (uint32_t)c16 * 16;
            size_t gA = (size_t)(row0 + rw) * ldx + kk0 + c16 * 8;
            size_t gB = (size_t)(col0 + rw) * ldx + kk0 + c16 * 8;
            cp16(stg + OFF_AHI + soff, aH + gA);
            cp16(stg + OFF_ALO + soff, aL + gA);
            cp16(stg + OFF_BHI + soff, bH + gB);
            cp16(stg + OFF_BLO + soff, bL + gB);
        }
        CP_COMMIT();
    };

    issue_cp(0, sb + 1024);

    // ldmatrix per-lane base offsets (within a stage)
    const uint32_t aoff = (uint32_t)(warp_m * 64 + (lane & 15)) * ROWB
                        + ((lane >> 4) & 1) * 16;
    const uint32_t boff = (uint32_t)(warp_n * 32 + (lane & 7) + (((lane >> 4) & 1) << 3)) * ROWB
                        + ((lane >> 3) & 1) * 16;

    for (int kt = 0; kt < KTILES; kt++) {
        const uint32_t stg = sb + 1024 + (uint32_t)(kt & 1) * STG_SZ;
        if (kt + 1 < KTILES) {
            issue_cp(kt + 1, sb + 1024 + (uint32_t)((kt + 1) & 1) * STG_SZ);
            CP_WAIT(1);
        } else {
            CP_WAIT(0);
        }
        __syncthreads();

#pragma unroll
        for (int s = 0; s < 2; s++) {
            const uint32_t ks = s * 32;        // byte offset of the k16 half
            uint32_t bh[8], bl[8], afr[16];
            ldsm4(bh + 0, stg + OFF_BHI + boff + ks);
            ldsm4(bh + 4, stg + OFF_BHI + boff + 16 * ROWB + ks);
            ldsm4(bl + 0, stg + OFF_BLO + boff + ks);
            ldsm4(bl + 4, stg + OFF_BLO + boff + 16 * ROWB + ks);
#pragma unroll
            for (int i = 0; i < 4; i++)
                ldsm4(afr + i * 4, stg + OFF_AHI + aoff + (uint32_t)i * 16 * ROWB + ks);
#pragma unroll
            for (int i = 0; i < 4; i++)
#pragma unroll
                for (int j = 0; j < 4; j++)
                    mma_bf16(acc[i][j], afr + i * 4, bh + j * 2);
#pragma unroll
            for (int i = 0; i < 4; i++)
#pragma unroll
                for (int j = 0; j < 4; j++)
                    mma_bf16(acc[i][j], afr + i * 4, bl + j * 2);
#pragma unroll
            for (int i = 0; i < 4; i++)
                ldsm4(afr + i * 4, stg + OFF_ALO + aoff + (uint32_t)i * 16 * ROWB + ks);
#pragma unroll
            for (int i = 0; i < 4; i++)
#pragma unroll
                for (int j = 0; j < 4; j++)
                    mma_bf16(acc[i][j], afr + i * 4, bh + j * 2);
        }
        __syncthreads();
    }

    // epilogue
    const int r_base = row0 + warp_m * 64 + (lane >> 2);
    const int c_base = warp_n * 32 + (lane & 3) * 2;
#pragma unroll
    for (int i = 0; i < 4; i++) {
#pragma unroll
        for (int j = 0; j < 4; j++) {
            int r = r_base + i * 16;
            int c = c_base + j * 8;
            float b0 = bias_s[c], b1 = bias_s[c + 1];
            float2 v0 = make_float2(acc[i][j][0] + b0, acc[i][j][1] + b1);
            float2 v1 = make_float2(acc[i][j][2] + b0, acc[i][j][3] + b1);
            *(float2*)(out + (size_t)r * DOUT + col0 + c) = v0;
            *(float2*)(out + (size_t)(r + 8) * DOUT + col0 + c) = v1;
        }
    }
}

// ---------------------------------------------------------------------------
// Launch (6 kernels; profiler -s 5 lands on k_out_mma)
// ---------------------------------------------------------------------------
extern "C" void kernel_launch(void* const* d_in, const int* in_sizes, int n_in,
                              void* d_out, int out_size) {
    const float* x     = (const float*)d_in[0];
    const float* s_re  = (const float*)d_in[1];
    const float* s_im  = (const float*)d_in[2];
    const int*   start = (const int*)d_in[3];
    const float* Wpre  = (const float*)d_in[5];
    const float* bpre  = (const float*)d_in[6];
    const float* Wskip = (const float*)d_in[7];
    const float* bskip = (const float*)d_in[8];
    const float* Wmix  = (const float*)d_in[9];
    const float* bmix  = (const float*)d_in[10];
    const float* a     = (const float*)d_in[11];
    const float* bf    = (const float*)d_in[12];
    float* out = (float*)d_out;
    float* stateOut = out + (size_t)TT * DOUT;  // planar: 1024 re then 1024 im

    cudaFuncSetAttribute(k_out_mma, cudaFuncAttributeMaxDynamicSharedMemorySize, SM_TOTAL);

    k_split<<<(N4_ALL + 255) / 256, 256>>>(x, Wmix, Wskip);
    k_pre<<<TT / 64, 256>>>(x, Wpre, bpre);
    k_chunk<<<NCHUNK, 256>>>(start, a, bf);
    k_chain<<<1, NCH>>>(s_re, s_im, a, bf, stateOut);
    k_emit<<<NCHUNK, 256>>>(start, a, bf);
    dim3 g3(DOUT / 128, TT / 128);
    k_out_mma<<<g3, 256, SM_TOTAL>>>(bmix, bskip, out);
}

// round 7
// speedup vs baseline: 2.2694x; 1.0120x over previous
#include <cuda_runtime.h>
#include <cuda_bf16.h>
#include <math.h>
#include <stdint.h>

#define TT      8192
#define DIN     1024
#define DOUT    1024
#define MTR     64
#define CCT     16
#define NCH     1024
#define CHUNK   32
#define NCHUNK  256           // TT/CHUNK
#define DMIX    2048
#define KTOT    (DMIX + DIN)  // 3072

// Scratch
__device__ float g_pre[TT * MTR];
__device__ float g_Bre[NCHUNK * NCH];
__device__ float g_Bim[NCHUNK * NCH];
__device__ float g_cRe[NCHUNK * NCH];
__device__ float g_cIm[NCHUNK * NCH];
__device__ int   g_any[NCHUNK];
// bf16 hi/lo planes for the big GEMM
__device__ __nv_bfloat16 g_zinH[TT * DMIX];
__device__ __nv_bfloat16 g_zinL[TT * DMIX];
__device__ __nv_bfloat16 g_xH[TT * DIN];
__device__ __nv_bfloat16 g_xL[TT * DIN];
__device__ __nv_bfloat16 g_wmH[DOUT * DMIX];
__device__ __nv_bfloat16 g_wmL[DOUT * DMIX];
__device__ __nv_bfloat16 g_wsH[DOUT * DIN];
__device__ __nv_bfloat16 g_wsL[DOUT * DIN];

// ---------------------------------------------------------------------------
// helpers
// ---------------------------------------------------------------------------
__device__ __forceinline__ uint32_t smem_u32(const void* p) {
    uint32_t a;
    asm("{ .reg .u64 t; cvta.to.shared.u64 t, %1; cvt.u32.u64 %0, t; }" : "=r"(a) : "l"(p));
    return a;
}
__device__ __forceinline__ void ldsm4(uint32_t* r, uint32_t addr) {
    asm volatile("ldmatrix.sync.aligned.m8n8.x4.shared.b16 {%0,%1,%2,%3}, [%4];"
                 : "=r"(r[0]), "=r"(r[1]), "=r"(r[2]), "=r"(r[3]) : "r"(addr));
}
__device__ __forceinline__ void mma_bf16(float* d, const uint32_t* a, const uint32_t* b) {
    asm volatile("mma.sync.aligned.m16n8k16.row.col.f32.bf16.bf16.f32 "
                 "{%0,%1,%2,%3}, {%4,%5,%6,%7}, {%8,%9}, {%0,%1,%2,%3};"
                 : "+f"(d[0]), "+f"(d[1]), "+f"(d[2]), "+f"(d[3])
                 : "r"(a[0]), "r"(a[1]), "r"(a[2]), "r"(a[3]), "r"(b[0]), "r"(b[1]));
}
__device__ __forceinline__ void cp16(uint32_t dst, const void* src) {
    asm volatile("cp.async.cg.shared.global [%0], [%1], 16;"
                 :: "r"(dst), "l"(src) : "memory");
}
#define CP_COMMIT() asm volatile("cp.async.commit_group;" ::: "memory")
#define CP_WAIT(n)  asm volatile("cp.async.wait_group %0;" :: "n"(n) : "memory")

__device__ __forceinline__ void splitbf(float v, __nv_bfloat16& h, __nv_bfloat16& l) {
    h = __float2bfloat16_rn(v);
    l = __float2bfloat16_rn(v - __bfloat162float(h));
}
__device__ __forceinline__ uint32_t pack2(__nv_bfloat16 a, __nv_bfloat16 b) {
    return (uint32_t)__bfloat16_as_ushort(a) | ((uint32_t)__bfloat16_as_ushort(b) << 16);
}

// ---------------------------------------------------------------------------
// K0: fused splitter for x, Wmix, Wskip -> bf16 hi/lo planes
// ---------------------------------------------------------------------------
#define N4_X   (TT * DIN / 4)
#define N4_WM  (DOUT * DMIX / 4)
#define N4_WS  (DOUT * DIN / 4)
#define N4_ALL (N4_X + N4_WM + N4_WS)

__global__ __launch_bounds__(256) void k_split(const float* __restrict__ x,
                                               const float* __restrict__ Wmix,
                                               const float* __restrict__ Wskip) {
    int i = blockIdx.x * blockDim.x + threadIdx.x;
    if (i >= N4_ALL) return;
    const float* src; __nv_bfloat16 *dH, *dL; int j;
    if (i < N4_X)              { src = x;     dH = g_xH;  dL = g_xL;  j = i; }
    else if (i < N4_X + N4_WM) { src = Wmix;  dH = g_wmH; dL = g_wmL; j = i - N4_X; }
    else                       { src = Wskip; dH = g_wsH; dL = g_wsL; j = i - N4_X - N4_WM; }
    float4 v = ((const float4*)src)[j];
    __nv_bfloat16 h0, l0, h1, l1, h2, l2, h3, l3;
    splitbf(v.x, h0, l0); splitbf(v.y, h1, l1);
    splitbf(v.z, h2, l2); splitbf(v.w, h3, l3);
    ((uint2*)dH)[j] = make_uint2(pack2(h0, h1), pack2(h2, h3));
    ((uint2*)dL)[j] = make_uint2(pack2(l0, l1), pack2(l2, l3));
}

// ---------------------------------------------------------------------------
// K1: pre = rownorm(x @ W_pre^T + b_pre)
// ---------------------------------------------------------------------------
__global__ __launch_bounds__(256) void k_pre(const float* __restrict__ x,
                                             const float* __restrict__ Wp,
                                             const float* __restrict__ bp) {
    __shared__ float xs[32][65];
    __shared__ float ws[32][65];
    __shared__ float nrm[64];
    const int tid = threadIdx.x;
    const int ty = tid >> 4, tx = tid & 15;
    const int row0 = blockIdx.x * 64;

    float acc[4][4];
#pragma unroll
    for (int i = 0; i < 4; i++)
#pragma unroll
        for (int j = 0; j < 4; j++) acc[i][j] = 0.f;

    for (int k0 = 0; k0 < DIN; k0 += 32) {
#pragma unroll
        for (int r = 0; r < 8; r++) {
            int idx = tid + r * 256;
            int m = idx >> 5, k = idx & 31;
            xs[k][m] = x[(size_t)(row0 + m) * DIN + k0 + k];
            ws[k][m] = Wp[(size_t)m * DIN + k0 + k];
        }
        __syncthreads();
#pragma unroll
        for (int kk = 0; kk < 32; kk++) {
            float av[4], bv[4];
#pragma unroll
            for (int i = 0; i < 4; i++) av[i] = xs[kk][ty * 4 + i];
#pragma unroll
            for (int j = 0; j < 4; j++) bv[j] = ws[kk][tx * 4 + j];
#pragma unroll
            for (int i = 0; i < 4; i++)
#pragma unroll
                for (int j = 0; j < 4; j++) acc[i][j] += av[i] * bv[j];
        }
        __syncthreads();
    }
#pragma unroll
    for (int j = 0; j < 4; j++) {
        float b = bp[tx * 4 + j];
#pragma unroll
        for (int i = 0; i < 4; i++) acc[i][j] += b;
    }
    if (tid < 64) nrm[tid] = 0.f;
    __syncthreads();
#pragma unroll
    for (int i = 0; i < 4; i++) {
        float s = 0.f;
#pragma unroll
        for (int j = 0; j < 4; j++) s += acc[i][j] * acc[i][j];
        atomicAdd(&nrm[ty * 4 + i], s);
    }
    __syncthreads();
#pragma unroll
    for (int i = 0; i < 4; i++) {
        float inv = 1.0f / (1e-6f + sqrtf(nrm[ty * 4 + i]));
#pragma unroll
        for (int j = 0; j < 4; j++)
            g_pre[(size_t)(row0 + ty * 4 + i) * MTR + tx * 4 + j] = acc[i][j] * inv;
    }
}

// ---------------------------------------------------------------------------
// K2a: per-chunk local scan from S=0 -> transfer (B, anyStart).  CHUNK=32.
// ---------------------------------------------------------------------------
__global__ __launch_bounds__(256) void k_chunk(const int* __restrict__ start,
                                               const float* __restrict__ a,
                                               const float* __restrict__ bfreq) {
    __shared__ float sp[CHUNK][MTR];
    __shared__ int ss[CHUNK];
    __shared__ int sAny;
    const int tid = threadIdx.x;
    const int ck = blockIdx.x;
    const int t0 = ck * CHUNK;

    for (int idx = tid; idx < CHUNK * MTR; idx += 256)
        sp[idx >> 6][idx & 63] = g_pre[(size_t)(t0 + (idx >> 6)) * MTR + (idx & 63)];
    if (tid < CHUNK) ss[tid] = (start[t0 + tid] != 0);
    if (tid == 0) sAny = 0;
    __syncthreads();
    if (tid < CHUNK && ss[tid]) atomicOr(&sAny, 1);

    const int m = tid >> 2;
    const float gmag = expf(-fabsf(a[m]));
    float gre[4], gim[4], Sre[4], Sim[4];
#pragma unroll
    for (int q = 0; q < 4; q++) {
        int c = ((tid & 3) << 2) + q;
        float sv, cv; sincosf(bfreq[c], &sv, &cv);
        gre[q] = gmag * cv; gim[q] = gmag * sv;
        Sre[q] = 0.f; Sim[q] = 0.f;
    }
    for (int t = 0; t < CHUNK; t++) {
        float p = sp[t][m];
        float keep = ss[t] ? 0.f : 1.f;
#pragma unroll
        for (int q = 0; q < 4; q++) {
            float r  = keep * (gre[q] * Sre[q] - gim[q] * Sim[q]) + p;
            float im = keep * (gre[q] * Sim[q] + gim[q] * Sre[q]);
            Sre[q] = r; Sim[q] = im;
        }
    }
#pragma unroll
    for (int q = 0; q < 4; q++) {
        int ch = tid * 4 + q;
        g_Bre[(size_t)ck * NCH + ch] = Sre[q];
        g_Bim[(size_t)ck * NCH + ch] = Sim[q];
    }
    __syncthreads();
    if (tid == 0) g_any[ck] = sAny;
}

// ---------------------------------------------------------------------------
// K2b: sequential chain over 256 chunks, batched prefetch (MLP=16).
// ---------------------------------------------------------------------------
#define CB 16
__global__ __launch_bounds__(1024) void k_chain(const float* __restrict__ s_re0,
                                                const float* __restrict__ s_im0,
                                                const float* __restrict__ a,
                                                const float* __restrict__ bfreq,
                                                float* stateOut) {
    __shared__ float keep_s[NCHUNK];
    const int ch = threadIdx.x;
    const int m = ch >> 4, c = ch & 15;
    if (ch < NCHUNK) keep_s[ch] = g_any[ch] ? 0.f : 1.f;
    __syncthreads();

    const float Amag = expf(-(float)CHUNK * fabsf(a[m]));
    float sv, cv; sincosf((float)CHUNK * bfreq[c], &sv, &cv);
    const float Are = Amag * cv, Aim = Amag * sv;
    float Sre = s_re0[ch], Sim = s_im0[ch];

    for (int kb = 0; kb < NCHUNK; kb += CB) {
        float br[CB], bi[CB];
#pragma unroll
        for (int q = 0; q < CB; q++) {
            br[q] = g_Bre[(size_t)(kb + q) * NCH + ch];
            bi[q] = g_Bim[(size_t)(kb + q) * NCH + ch];
        }
#pragma unroll
        for (int q = 0; q < CB; q++) {
            g_cRe[(size_t)(kb + q) * NCH + ch] = Sre;
            g_cIm[(size_t)(kb + q) * NCH + ch] = Sim;
            float keep = keep_s[kb + q];
            float r  = keep * (Are * Sre - Aim * Sim) + br[q];
            float im = keep * (Are * Sim + Aim * Sre) + bi[q];
            Sre = r; Sim = im;
        }
    }
    stateOut[ch]       = Sre;   // planar: re then im
    stateOut[NCH + ch] = Sim;
}

// ---------------------------------------------------------------------------
// K2c: re-scan with true carry, emit zin as bf16 hi/lo planes.  CHUNK=32.
// ---------------------------------------------------------------------------
__global__ __launch_bounds__(256) void k_emit(const int* __restrict__ start,
                                              const float* __restrict__ a,
                                              const float* __restrict__ bfreq) {
    __shared__ float sp[CHUNK][MTR];
    __shared__ int ss[CHUNK];
    const int tid = threadIdx.x;
    const int ck = blockIdx.x;
    const int t0 = ck * CHUNK;

    for (int idx = tid; idx < CHUNK * MTR; idx += 256)
        sp[idx >> 6][idx & 63] = g_pre[(size_t)(t0 + (idx >> 6)) * MTR + (idx & 63)];
    if (tid < CHUNK) ss[tid] = (start[t0 + tid] != 0);
    __syncthreads();

    const int m = tid >> 2;
    const int cg = tid & 3;
    const float gmag = expf(-fabsf(a[m]));
    float gre[4], gim[4], Sre[4], Sim[4];
#pragma unroll
    for (int q = 0; q < 4; q++) {
        int c = cg * 4 + q;
        float sv, cv; sincosf(bfreq[c], &sv, &cv);
        gre[q] = gmag * cv; gim[q] = gmag * sv;
        int ch = m * CCT + c;
        Sre[q] = g_cRe[(size_t)ck * NCH + ch];
        Sim[q] = g_cIm[(size_t)ck * NCH + ch];
    }
    for (int t = 0; t < CHUNK; t++) {
        float p = sp[t][m];
        float keep = ss[t] ? 0.f : 1.f;
#pragma unroll
        for (int q = 0; q < 4; q++) {
            float r  = keep * (gre[q] * Sre[q] - gim[q] * Sim[q]) + p;
            float im = keep * (gre[q] * Sim[q] + gim[q] * Sre[q]);
            Sre[q] = r; Sim[q] = im;
        }
        size_t base = (size_t)(t0 + t) * DMIX + (size_t)m * 32 + cg * 4;
        __nv_bfloat16 h[8], l[8];
#pragma unroll
        for (int q = 0; q < 4; q++) { splitbf(Sre[q], h[q], l[q]); }
#pragma unroll
        for (int q = 0; q < 4; q++) { splitbf(Sim[q], h[4 + q], l[4 + q]); }
        *(uint2*)(g_zinH + base)      = make_uint2(pack2(h[0], h[1]), pack2(h[2], h[3]));
        *(uint2*)(g_zinH + base + 16) = make_uint2(pack2(h[4], h[5]), pack2(h[6], h[7]));
        *(uint2*)(g_zinL + base)      = make_uint2(pack2(l[0], l[1]), pack2(l[2], l[3]));
        *(uint2*)(g_zinL + base + 16) = make_uint2(pack2(l[4], l[5]), pack2(l[6], l[7]));
    }
}

// ---------------------------------------------------------------------------
// K3: out = z_in @ Wmix^T + x @ Wskip^T + biases (bf16-split mma.sync).
// ---------------------------------------------------------------------------
#define ROWB     80
#define OFF_AHI  0
#define OFF_ALO  10240
#define OFF_BHI  20480
#define OFF_BLO  30720
#define STG_SZ   40960
#define SM_TOTAL (1024 + 2 * STG_SZ)
#define KTILES   (KTOT / 32)              // 96
#define MIXTILES (DMIX / 32)              // 64

__global__ __launch_bounds__(256, 2) void k_out_mma(const float* __restrict__ bmix,
                                                    const float* __restrict__ bskip,
                                                    float* __restrict__ out) {
    extern __shared__ char smem[];
    float* bias_s = (float*)smem;
    const uint32_t sb = smem_u32(smem);
    const int tid = threadIdx.x;
    const int lane = tid & 31, wid = tid >> 5;
    const int warp_m = wid & 1, warp_n = wid >> 1;
    const int row0 = blockIdx.y * 128;
    const int col0 = blockIdx.x * 128;

    if (tid < 128) bias_s[tid] = bmix[col0 + tid] + bskip[col0 + tid];

    float acc[4][4][4];
#pragma unroll
    for (int i = 0; i < 4; i++)
#pragma unroll
        for (int j = 0; j < 4; j++)
#pragma unroll
            for (int q = 0; q < 4; q++) acc[i][j][q] = 0.f;

    auto issue_cp = [&](int kt, uint32_t stg) {
        const bool mix = kt < MIXTILES;
        const __nv_bfloat16* aH = mix ? g_zinH : g_xH;
        const __nv_bfloat16* aL = mix ? g_zinL : g_xL;
        const __nv_bfloat16* bH = mix ? g_wmH : g_wsH;
        const __nv_bfloat16* bL = mix ? g_wmL : g_wsL;
        const int ldx = mix ? DMIX : DIN;
        const int kk0 = mix ? kt * 32 : (kt - MIXTILES) * 32;
#pragma unroll
        for (int r = 0; r < 2; r++) {
            int ci = tid + r * 256;
            int rw = ci >> 2, c16 = ci & 3;
            uint32_t soff = (uint32_t)rw * ROWB + (uint32_t)c16 * 16;
            size_t gA = (size_t)(row0 + rw) * ldx + kk0 + c16 * 8;
            size_t gB = (size_t)(col0 + rw) * ldx + kk0 + c16 * 8;
            cp16(stg + OFF_AHI + soff, aH + gA);
            cp16(stg + OFF_ALO + soff, aL + gA);
            cp16(stg + OFF_BHI + soff, bH + gB);
            cp16(stg + OFF_BLO + soff, bL + gB);
        }
        CP_COMMIT();
    };

    issue_cp(0, sb + 1024);

    const uint32_t aoff = (uint32_t)(warp_m * 64 + (lane & 15)) * ROWB
                        + ((lane >> 4) & 1) * 16;
    const uint32_t boff = (uint32_t)(warp_n * 32 + (lane & 7) + (((lane >> 4) & 1) << 3)) * ROWB
                        + ((lane >> 3) & 1) * 16;

    for (int kt = 0; kt < KTILES; kt++) {
        const uint32_t stg = sb + 1024 + (uint32_t)(kt & 1) * STG_SZ;
        if (kt + 1 < KTILES) {
            issue_cp(kt + 1, sb + 1024 + (uint32_t)((kt + 1) & 1) * STG_SZ);
            CP_WAIT(1);
        } else {
            CP_WAIT(0);
        }
        __syncthreads();

#pragma unroll
        for (int s = 0; s < 2; s++) {
            const uint32_t ks = s * 32;
            uint32_t bh[8], bl[8], afr[16];
            ldsm4(bh + 0, stg + OFF_BHI + boff + ks);
            ldsm4(bh + 4, stg + OFF_BHI + boff + 16 * ROWB + ks);
            ldsm4(bl + 0, stg + OFF_BLO + boff + ks);
            ldsm4(bl + 4, stg + OFF_BLO + boff + 16 * ROWB + ks);
#pragma unroll
            for (int i = 0; i < 4; i++)
                ldsm4(afr + i * 4, stg + OFF_AHI + aoff + (uint32_t)i * 16 * ROWB + ks);
#pragma unroll
            for (int i = 0; i < 4; i++)
#pragma unroll
                for (int j = 0; j < 4; j++)
                    mma_bf16(acc[i][j], afr + i * 4, bh + j * 2);
#pragma unroll
            for (int i = 0; i < 4; i++)
#pragma unroll
                for (int j = 0; j < 4; j++)
                    mma_bf16(acc[i][j], afr + i * 4, bl + j * 2);
#pragma unroll
            for (int i = 0; i < 4; i++)
                ldsm4(afr + i * 4, stg + OFF_ALO + aoff + (uint32_t)i * 16 * ROWB + ks);
#pragma unroll
            for (int i = 0; i < 4; i++)
#pragma unroll
                for (int j = 0; j < 4; j++)
                    mma_bf16(acc[i][j], afr + i * 4, bh + j * 2);
        }
        __syncthreads();
    }

    const int r_base = row0 + warp_m * 64 + (lane >> 2);
    const int c_base = warp_n * 32 + (lane & 3) * 2;
#pragma unroll
    for (int i = 0; i < 4; i++) {
#pragma unroll
        for (int j = 0; j < 4; j++) {
            int r = r_base + i * 16;
            int c = c_base + j * 8;
            float b0 = bias_s[c], b1 = bias_s[c + 1];
            float2 v0 = make_float2(acc[i][j][0] + b0, acc[i][j][1] + b1);
            float2 v1 = make_float2(acc[i][j][2] + b0, acc[i][j][3] + b1);
            *(float2*)(out + (size_t)r * DOUT + col0 + c) = v0;
            *(float2*)(out + (size_t)(r + 8) * DOUT + col0 + c) = v1;
        }
    }
}

// ---------------------------------------------------------------------------
// Launch
// ---------------------------------------------------------------------------
extern "C" void kernel_launch(void* const* d_in, const int* in_sizes, int n_in,
                              void* d_out, int out_size) {
    const float* x     = (const float*)d_in[0];
    const float* s_re  = (const float*)d_in[1];
    const float* s_im  = (const float*)d_in[2];
    const int*   start = (const int*)d_in[3];
    const float* Wpre  = (const float*)d_in[5];
    const float* bpre  = (const float*)d_in[6];
    const float* Wskip = (const float*)d_in[7];
    const float* bskip = (const float*)d_in[8];
    const float* Wmix  = (const float*)d_in[9];
    const float* bmix  = (const float*)d_in[10];
    const float* a     = (const float*)d_in[11];
    const float* bf    = (const float*)d_in[12];
    float* out = (float*)d_out;
    float* stateOut = out + (size_t)TT * DOUT;

    cudaFuncSetAttribute(k_out_mma, cudaFuncAttributeMaxDynamicSharedMemorySize, SM_TOTAL);

    k_split<<<(N4_ALL + 255) / 256, 256>>>(x, Wmix, Wskip);
    k_pre<<<TT / 64, 256>>>(x, Wpre, bpre);
    k_chunk<<<NCHUNK, 256>>>(start, a, bf);
    k_chain<<<1, NCH>>>(s_re, s_im, a, bf, stateOut);
    k_emit<<<NCHUNK, 256>>>(start, a, bf);
    dim3 g3(DOUT / 128, TT / 128);
    k_out_mma<<<g3, 256, SM_TOTAL>>>(bmix, bskip, out);
}

// round 8
// speedup vs baseline: 2.3769x; 1.0474x over previous
#include <cuda_runtime.h>
#include <cuda_bf16.h>
#include <math.h>
#include <stdint.h>

#define TT      8192
#define DIN     1024
#define DOUT    1024
#define MTR     64
#define CCT     16
#define NCH     1024
#define CHUNK   32
#define NCHUNK  256           // TT/CHUNK
#define DMIX    2048
#define KTOT    (DMIX + DIN)  // 3072

// Scratch
__device__ float g_pre[TT * MTR];
__device__ float g_Bre[NCHUNK * NCH];
__device__ float g_Bim[NCHUNK * NCH];
__device__ float g_cRe[NCHUNK * NCH];
__device__ float g_cIm[NCHUNK * NCH];
__device__ int   g_any[NCHUNK];
// bf16 hi/lo planes for the big GEMM
__device__ __nv_bfloat16 g_zinH[TT * DMIX];
__device__ __nv_bfloat16 g_zinL[TT * DMIX];
__device__ __nv_bfloat16 g_xH[TT * DIN];
__device__ __nv_bfloat16 g_xL[TT * DIN];
__device__ __nv_bfloat16 g_wmH[DOUT * DMIX];
__device__ __nv_bfloat16 g_wmL[DOUT * DMIX];
__device__ __nv_bfloat16 g_wsH[DOUT * DIN];
__device__ __nv_bfloat16 g_wsL[DOUT * DIN];

// ---------------------------------------------------------------------------
// helpers
// ---------------------------------------------------------------------------
__device__ __forceinline__ uint32_t smem_u32(const void* p) {
    uint32_t a;
    asm("{ .reg .u64 t; cvta.to.shared.u64 t, %1; cvt.u32.u64 %0, t; }" : "=r"(a) : "l"(p));
    return a;
}
__device__ __forceinline__ void ldsm4(uint32_t* r, uint32_t addr) {
    asm volatile("ldmatrix.sync.aligned.m8n8.x4.shared.b16 {%0,%1,%2,%3}, [%4];"
                 : "=r"(r[0]), "=r"(r[1]), "=r"(r[2]), "=r"(r[3]) : "r"(addr));
}
__device__ __forceinline__ void mma_bf16(float* d, const uint32_t* a, const uint32_t* b) {
    asm volatile("mma.sync.aligned.m16n8k16.row.col.f32.bf16.bf16.f32 "
                 "{%0,%1,%2,%3}, {%4,%5,%6,%7}, {%8,%9}, {%0,%1,%2,%3};"
                 : "+f"(d[0]), "+f"(d[1]), "+f"(d[2]), "+f"(d[3])
                 : "r"(a[0]), "r"(a[1]), "r"(a[2]), "r"(a[3]), "r"(b[0]), "r"(b[1]));
}
__device__ __forceinline__ void cp16(uint32_t dst, const void* src) {
    asm volatile("cp.async.cg.shared.global [%0], [%1], 16;"
                 :: "r"(dst), "l"(src) : "memory");
}
#define CP_COMMIT() asm volatile("cp.async.commit_group;" ::: "memory")
#define CP_WAIT(n)  asm volatile("cp.async.wait_group %0;" :: "n"(n) : "memory")

__device__ __forceinline__ void splitbf(float v, __nv_bfloat16& h, __nv_bfloat16& l) {
    h = __float2bfloat16_rn(v);
    l = __float2bfloat16_rn(v - __bfloat162float(h));
}
__device__ __forceinline__ uint32_t pack2(__nv_bfloat16 a, __nv_bfloat16 b) {
    return (uint32_t)__bfloat16_as_ushort(a) | ((uint32_t)__bfloat16_as_ushort(b) << 16);
}

// ---------------------------------------------------------------------------
// K0: fused splitter for x, Wmix, Wskip -> bf16 hi/lo planes
// ---------------------------------------------------------------------------
#define N4_X   (TT * DIN / 4)
#define N4_WM  (DOUT * DMIX / 4)
#define N4_WS  (DOUT * DIN / 4)
#define N4_ALL (N4_X + N4_WM + N4_WS)

__global__ __launch_bounds__(256) void k_split(const float* __restrict__ x,
                                               const float* __restrict__ Wmix,
                                               const float* __restrict__ Wskip) {
    int i = blockIdx.x * blockDim.x + threadIdx.x;
    if (i >= N4_ALL) return;
    const float* src; __nv_bfloat16 *dH, *dL; int j;
    if (i < N4_X)              { src = x;     dH = g_xH;  dL = g_xL;  j = i; }
    else if (i < N4_X + N4_WM) { src = Wmix;  dH = g_wmH; dL = g_wmL; j = i - N4_X; }
    else                       { src = Wskip; dH = g_wsH; dL = g_wsL; j = i - N4_X - N4_WM; }
    float4 v = ((const float4*)src)[j];
    __nv_bfloat16 h0, l0, h1, l1, h2, l2, h3, l3;
    splitbf(v.x, h0, l0); splitbf(v.y, h1, l1);
    splitbf(v.z, h2, l2); splitbf(v.w, h3, l3);
    ((uint2*)dH)[j] = make_uint2(pack2(h0, h1), pack2(h2, h3));
    ((uint2*)dL)[j] = make_uint2(pack2(l0, l1), pack2(l2, l3));
}

// ---------------------------------------------------------------------------
// K1: pre = rownorm(x @ W_pre^T + b_pre)
// ---------------------------------------------------------------------------
__global__ __launch_bounds__(256) void k_pre(const float* __restrict__ x,
                                             const float* __restrict__ Wp,
                                             const float* __restrict__ bp) {
    __shared__ float xs[32][65];
    __shared__ float ws[32][65];
    __shared__ float nrm[64];
    const int tid = threadIdx.x;
    const int ty = tid >> 4, tx = tid & 15;
    const int row0 = blockIdx.x * 64;

    float acc[4][4];
#pragma unroll
    for (int i = 0; i < 4; i++)
#pragma unroll
        for (int j = 0; j < 4; j++) acc[i][j] = 0.f;

    for (int k0 = 0; k0 < DIN; k0 += 32) {
#pragma unroll
        for (int r = 0; r < 8; r++) {
            int idx = tid + r * 256;
            int m = idx >> 5, k = idx & 31;
            xs[k][m] = x[(size_t)(row0 + m) * DIN + k0 + k];
            ws[k][m] = Wp[(size_t)m * DIN + k0 + k];
        }
        __syncthreads();
#pragma unroll
        for (int kk = 0; kk < 32; kk++) {
            float av[4], bv[4];
#pragma unroll
            for (int i = 0; i < 4; i++) av[i] = xs[kk][ty * 4 + i];
#pragma unroll
            for (int j = 0; j < 4; j++) bv[j] = ws[kk][tx * 4 + j];
#pragma unroll
            for (int i = 0; i < 4; i++)
#pragma unroll
                for (int j = 0; j < 4; j++) acc[i][j] += av[i] * bv[j];
        }
        __syncthreads();
    }
#pragma unroll
    for (int j = 0; j < 4; j++) {
        float b = bp[tx * 4 + j];
#pragma unroll
        for (int i = 0; i < 4; i++) acc[i][j] += b;
    }
    if (tid < 64) nrm[tid] = 0.f;
    __syncthreads();
#pragma unroll
    for (int i = 0; i < 4; i++) {
        float s = 0.f;
#pragma unroll
        for (int j = 0; j < 4; j++) s += acc[i][j] * acc[i][j];
        atomicAdd(&nrm[ty * 4 + i], s);
    }
    __syncthreads();
#pragma unroll
    for (int i = 0; i < 4; i++) {
        float inv = 1.0f / (1e-6f + sqrtf(nrm[ty * 4 + i]));
#pragma unroll
        for (int j = 0; j < 4; j++)
            g_pre[(size_t)(row0 + ty * 4 + i) * MTR + tx * 4 + j] = acc[i][j] * inv;
    }
}

// ---------------------------------------------------------------------------
// K2a: per-chunk local scan from S=0 -> transfer (B, anyStart).  CHUNK=32.
// ---------------------------------------------------------------------------
__global__ __launch_bounds__(256) void k_chunk(const int* __restrict__ start,
                                               const float* __restrict__ a,
                                               const float* __restrict__ bfreq) {
    __shared__ float sp[CHUNK][MTR];
    __shared__ int ss[CHUNK];
    __shared__ int sAny;
    const int tid = threadIdx.x;
    const int ck = blockIdx.x;
    const int t0 = ck * CHUNK;

    for (int idx = tid; idx < CHUNK * MTR; idx += 256)
        sp[idx >> 6][idx & 63] = g_pre[(size_t)(t0 + (idx >> 6)) * MTR + (idx & 63)];
    if (tid < CHUNK) ss[tid] = (start[t0 + tid] != 0);
    if (tid == 0) sAny = 0;
    __syncthreads();
    if (tid < CHUNK && ss[tid]) atomicOr(&sAny, 1);

    const int m = tid >> 2;
    const float gmag = expf(-fabsf(a[m]));
    float gre[4], gim[4], Sre[4], Sim[4];
#pragma unroll
    for (int q = 0; q < 4; q++) {
        int c = ((tid & 3) << 2) + q;
        float sv, cv; sincosf(bfreq[c], &sv, &cv);
        gre[q] = gmag * cv; gim[q] = gmag * sv;
        Sre[q] = 0.f; Sim[q] = 0.f;
    }
    for (int t = 0; t < CHUNK; t++) {
        float p = sp[t][m];
        float keep = ss[t] ? 0.f : 1.f;
#pragma unroll
        for (int q = 0; q < 4; q++) {
            float r  = keep * (gre[q] * Sre[q] - gim[q] * Sim[q]) + p;
            float im = keep * (gre[q] * Sim[q] + gim[q] * Sre[q]);
            Sre[q] = r; Sim[q] = im;
        }
    }
#pragma unroll
    for (int q = 0; q < 4; q++) {
        int ch = tid * 4 + q;
        g_Bre[(size_t)ck * NCH + ch] = Sre[q];
        g_Bim[(size_t)ck * NCH + ch] = Sim[q];
    }
    __syncthreads();
    if (tid == 0) g_any[ck] = sAny;
}

// ---------------------------------------------------------------------------
// K2b: sequential chain, parallel over channels: 16 blocks x 64 channels.
// ---------------------------------------------------------------------------
#define CB 16
__global__ __launch_bounds__(64) void k_chain(const float* __restrict__ s_re0,
                                              const float* __restrict__ s_im0,
                                              const float* __restrict__ a,
                                              const float* __restrict__ bfreq,
                                              float* stateOut) {
    __shared__ float keep_s[NCHUNK];
    const int ch = blockIdx.x * 64 + threadIdx.x;
    const int m = ch >> 4, c = ch & 15;
    for (int idx = threadIdx.x; idx < NCHUNK; idx += 64)
        keep_s[idx] = g_any[idx] ? 0.f : 1.f;
    __syncthreads();

    const float Amag = expf(-(float)CHUNK * fabsf(a[m]));
    float sv, cv; sincosf((float)CHUNK * bfreq[c], &sv, &cv);
    const float Are = Amag * cv, Aim = Amag * sv;
    float Sre = s_re0[ch], Sim = s_im0[ch];

    for (int kb = 0; kb < NCHUNK; kb += CB) {
        float br[CB], bi[CB];
#pragma unroll
        for (int q = 0; q < CB; q++) {
            br[q] = g_Bre[(size_t)(kb + q) * NCH + ch];
            bi[q] = g_Bim[(size_t)(kb + q) * NCH + ch];
        }
#pragma unroll
        for (int q = 0; q < CB; q++) {
            g_cRe[(size_t)(kb + q) * NCH + ch] = Sre;
            g_cIm[(size_t)(kb + q) * NCH + ch] = Sim;
            float keep = keep_s[kb + q];
            float r  = keep * (Are * Sre - Aim * Sim) + br[q];
            float im = keep * (Are * Sim + Aim * Sre) + bi[q];
            Sre = r; Sim = im;
        }
    }
    stateOut[ch]       = Sre;   // planar: re then im
    stateOut[NCH + ch] = Sim;
}

// ---------------------------------------------------------------------------
// K2c: re-scan with true carry, emit zin as bf16 hi/lo planes.  CHUNK=32.
// ---------------------------------------------------------------------------
__global__ __launch_bounds__(256) void k_emit(const int* __restrict__ start,
                                              const float* __restrict__ a,
                                              const float* __restrict__ bfreq) {
    __shared__ float sp[CHUNK][MTR];
    __shared__ int ss[CHUNK];
    const int tid = threadIdx.x;
    const int ck = blockIdx.x;
    const int t0 = ck * CHUNK;

    for (int idx = tid; idx < CHUNK * MTR; idx += 256)
        sp[idx >> 6][idx & 63] = g_pre[(size_t)(t0 + (idx >> 6)) * MTR + (idx & 63)];
    if (tid < CHUNK) ss[tid] = (start[t0 + tid] != 0);
    __syncthreads();

    const int m = tid >> 2;
    const int cg = tid & 3;
    const float gmag = expf(-fabsf(a[m]));
    float gre[4], gim[4], Sre[4], Sim[4];
#pragma unroll
    for (int q = 0; q < 4; q++) {
        int c = cg * 4 + q;
        float sv, cv; sincosf(bfreq[c], &sv, &cv);
        gre[q] = gmag * cv; gim[q] = gmag * sv;
        int ch = m * CCT + c;
        Sre[q] = g_cRe[(size_t)ck * NCH + ch];
        Sim[q] = g_cIm[(size_t)ck * NCH + ch];
    }
    for (int t = 0; t < CHUNK; t++) {
        float p = sp[t][m];
        float keep = ss[t] ? 0.f : 1.f;
#pragma unroll
        for (int q = 0; q < 4; q++) {
            float r  = keep * (gre[q] * Sre[q] - gim[q] * Sim[q]) + p;
            float im = keep * (gre[q] * Sim[q] + gim[q] * Sre[q]);
            Sre[q] = r; Sim[q] = im;
        }
        size_t base = (size_t)(t0 + t) * DMIX + (size_t)m * 32 + cg * 4;
        __nv_bfloat16 h[8], l[8];
#pragma unroll
        for (int q = 0; q < 4; q++) { splitbf(Sre[q], h[q], l[q]); }
#pragma unroll
        for (int q = 0; q < 4; q++) { splitbf(Sim[q], h[4 + q], l[4 + q]); }
        *(uint2*)(g_zinH + base)      = make_uint2(pack2(h[0], h[1]), pack2(h[2], h[3]));
        *(uint2*)(g_zinH + base + 16) = make_uint2(pack2(h[4], h[5]), pack2(h[6], h[7]));
        *(uint2*)(g_zinL + base)      = make_uint2(pack2(l[0], l[1]), pack2(l[2], l[3]));
        *(uint2*)(g_zinL + base + 16) = make_uint2(pack2(l[4], l[5]), pack2(l[6], l[7]));
    }
}

// no-op spacer so ncu's fixed skip lands on k_out_mma (launch #9)
__global__ void k_nop() {}

// ---------------------------------------------------------------------------
// K3: out = z_in @ Wmix^T + x @ Wskip^T + biases (bf16-split mma.sync).
// ---------------------------------------------------------------------------
#define ROWB     80
#define OFF_AHI  0
#define OFF_ALO  10240
#define OFF_BHI  20480
#define OFF_BLO  30720
#define STG_SZ   40960
#define SM_TOTAL (1024 + 2 * STG_SZ)
#define KTILES   (KTOT / 32)              // 96
#define MIXTILES (DMIX / 32)              // 64

__global__ __launch_bounds__(256, 2) void k_out_mma(const float* __restrict__ bmix,
                                                    const float* __restrict__ bskip,
                                                    float* __restrict__ out) {
    extern __shared__ char smem[];
    float* bias_s = (float*)smem;
    const uint32_t sb = smem_u32(smem);
    const int tid = threadIdx.x;
    const int lane = tid & 31, wid = tid >> 5;
    const int warp_m = wid & 1, warp_n = wid >> 1;
    const int row0 = blockIdx.y * 128;
    const int col0 = blockIdx.x * 128;

    if (tid < 128) bias_s[tid] = bmix[col0 + tid] + bskip[col0 + tid];

    float acc[4][4][4];
#pragma unroll
    for (int i = 0; i < 4; i++)
#pragma unroll
        for (int j = 0; j < 4; j++)
#pragma unroll
            for (int q = 0; q < 4; q++) acc[i][j][q] = 0.f;

    auto issue_cp = [&](int kt, uint32_t stg) {
        const bool mix = kt < MIXTILES;
        const __nv_bfloat16* aH = mix ? g_zinH : g_xH;
        const __nv_bfloat16* aL = mix ? g_zinL : g_xL;
        const __nv_bfloat16* bH = mix ? g_wmH : g_wsH;
        const __nv_bfloat16* bL = mix ? g_wmL : g_wsL;
        const int ldx = mix ? DMIX : DIN;
        const int kk0 = mix ? kt * 32 : (kt - MIXTILES) * 32;
#pragma unroll
        for (int r = 0; r < 2; r++) {
            int ci = tid + r * 256;
            int rw = ci >> 2, c16 = ci & 3;
            uint32_t soff = (uint32_t)rw * ROWB + (uint32_t)c16 * 16;
            size_t gA = (size_t)(row0 + rw) * ldx + kk0 + c16 * 8;
            size_t gB = (size_t)(col0 + rw) * ldx + kk0 + c16 * 8;
            cp16(stg + OFF_AHI + soff, aH + gA);
            cp16(stg + OFF_ALO + soff, aL + gA);
            cp16(stg + OFF_BHI + soff, bH + gB);
            cp16(stg + OFF_BLO + soff, bL + gB);
        }
        CP_COMMIT();
    };

    issue_cp(0, sb + 1024);

    const uint32_t aoff = (uint32_t)(warp_m * 64 + (lane & 15)) * ROWB
                        + ((lane >> 4) & 1) * 16;
    const uint32_t boff = (uint32_t)(warp_n * 32 + (lane & 7) + (((lane >> 4) & 1) << 3)) * ROWB
                        + ((lane >> 3) & 1) * 16;

    for (int kt = 0; kt < KTILES; kt++) {
        const uint32_t stg = sb + 1024 + (uint32_t)(kt & 1) * STG_SZ;
        if (kt + 1 < KTILES) {
            issue_cp(kt + 1, sb + 1024 + (uint32_t)((kt + 1) & 1) * STG_SZ);
            CP_WAIT(1);
        } else {
            CP_WAIT(0);
        }
        __syncthreads();

#pragma unroll
        for (int s = 0; s < 2; s++) {
            const uint32_t ks = s * 32;
            uint32_t bh[8], bl[8], afr[16];
            ldsm4(bh + 0, stg + OFF_BHI + boff + ks);
            ldsm4(bh + 4, stg + OFF_BHI + boff + 16 * ROWB + ks);
            ldsm4(bl + 0, stg + OFF_BLO + boff + ks);
            ldsm4(bl + 4, stg + OFF_BLO + boff + 16 * ROWB + ks);
#pragma unroll
            for (int i = 0; i < 4; i++)
                ldsm4(afr + i * 4, stg + OFF_AHI + aoff + (uint32_t)i * 16 * ROWB + ks);
#pragma unroll
            for (int i = 0; i < 4; i++)
#pragma unroll
                for (int j = 0; j < 4; j++)
                    mma_bf16(acc[i][j], afr + i * 4, bh + j * 2);
#pragma unroll
            for (int i = 0; i < 4; i++)
#pragma unroll
                for (int j = 0; j < 4; j++)
                    mma_bf16(acc[i][j], afr + i * 4, bl + j * 2);
#pragma unroll
            for (int i = 0; i < 4; i++)
                ldsm4(afr + i * 4, stg + OFF_ALO + aoff + (uint32_t)i * 16 * ROWB + ks);
#pragma unroll
            for (int i = 0; i < 4; i++)
#pragma unroll
                for (int j = 0; j < 4; j++)
                    mma_bf16(acc[i][j], afr + i * 4, bh + j * 2);
        }
        __syncthreads();
    }

    const int r_base = row0 + warp_m * 64 + (lane >> 2);
    const int c_base = warp_n * 32 + (lane & 3) * 2;
#pragma unroll
    for (int i = 0; i < 4; i++) {
#pragma unroll
        for (int j = 0; j < 4; j++) {
            int r = r_base + i * 16;
            int c = c_base + j * 8;
            float b0 = bias_s[c], b1 = bias_s[c + 1];
            float2 v0 = make_float2(acc[i][j][0] + b0, acc[i][j][1] + b1);
            float2 v1 = make_float2(acc[i][j][2] + b0, acc[i][j][3] + b1);
            *(float2*)(out + (size_t)r * DOUT + col0 + c) = v0;
            *(float2*)(out + (size_t)(r + 8) * DOUT + col0 + c) = v1;
        }
    }
}

// ---------------------------------------------------------------------------
// Launch (k_out_mma is the 9th launch -> ncu's fixed skip hits it)
// ---------------------------------------------------------------------------
extern "C" void kernel_launch(void* const* d_in, const int* in_sizes, int n_in,
                              void* d_out, int out_size) {
    const float* x     = (const float*)d_in[0];
    const float* s_re  = (const float*)d_in[1];
    const float* s_im  = (const float*)d_in[2];
    const int*   start = (const int*)d_in[3];
    const float* Wpre  = (const float*)d_in[5];
    const float* bpre  = (const float*)d_in[6];
    const float* Wskip = (const float*)d_in[7];
    const float* bskip = (const float*)d_in[8];
    const float* Wmix  = (const float*)d_in[9];
    const float* bmix  = (const float*)d_in[10];
    const float* a     = (const float*)d_in[11];
    const float* bf    = (const float*)d_in[12];
    float* out = (float*)d_out;
    float* stateOut = out + (size_t)TT * DOUT;

    cudaFuncSetAttribute(k_out_mma, cudaFuncAttributeMaxDynamicSharedMemorySize, SM_TOTAL);

    k_split<<<(N4_ALL + 255) / 256, 256>>>(x, Wmix, Wskip);
    k_pre<<<TT / 64, 256>>>(x, Wpre, bpre);
    k_chunk<<<NCHUNK, 256>>>(start, a, bf);
    k_chain<<<NCH / 64, 64>>>(s_re, s_im, a, bf, stateOut);
    k_emit<<<NCHUNK, 256>>>(start, a, bf);
    k_nop<<<1, 32>>>();
    k_nop<<<1, 32>>>();
    k_nop<<<1, 32>>>();
    dim3 g3(DOUT / 128, TT / 128);
    k_out_mma<<<g3, 256, SM_TOTAL>>>(bmix, bskip, out);
}

// round 9
// speedup vs baseline: 2.4189x; 1.0177x over previous
#include <cuda_runtime.h>
#include <cuda_bf16.h>
#include <math.h>
#include <stdint.h>

#define TT      8192
#define DIN     1024
#define DOUT    1024
#define MTR     64
#define CCT     16
#define NCH     1024
#define CHUNK   32
#define NCHUNK  256           // TT/CHUNK
#define DMIX    2048
#define KTOT    (DMIX + DIN)  // 3072

// Scratch
__device__ float g_pre[TT * MTR];
__device__ float g_Bre[NCHUNK * NCH];
__device__ float g_Bim[NCHUNK * NCH];
__device__ float g_cRe[NCHUNK * NCH];
__device__ float g_cIm[NCHUNK * NCH];
__device__ int   g_any[NCHUNK];
// bf16 hi/lo planes for the big GEMM
__device__ __nv_bfloat16 g_zinH[TT * DMIX];
__device__ __nv_bfloat16 g_zinL[TT * DMIX];
__device__ __nv_bfloat16 g_xH[TT * DIN];
__device__ __nv_bfloat16 g_xL[TT * DIN];
__device__ __nv_bfloat16 g_wmH[DOUT * DMIX];
__device__ __nv_bfloat16 g_wmL[DOUT * DMIX];
__device__ __nv_bfloat16 g_wsH[DOUT * DIN];
__device__ __nv_bfloat16 g_wsL[DOUT * DIN];

// ---------------------------------------------------------------------------
// helpers
// ---------------------------------------------------------------------------
__device__ __forceinline__ uint32_t smem_u32(const void* p) {
    uint32_t a;
    asm("{ .reg .u64 t; cvta.to.shared.u64 t, %1; cvt.u32.u64 %0, t; }" : "=r"(a) : "l"(p));
    return a;
}
__device__ __forceinline__ void ldsm4(uint32_t* r, uint32_t addr) {
    asm volatile("ldmatrix.sync.aligned.m8n8.x4.shared.b16 {%0,%1,%2,%3}, [%4];"
                 : "=r"(r[0]), "=r"(r[1]), "=r"(r[2]), "=r"(r[3]) : "r"(addr));
}
__device__ __forceinline__ void mma_bf16(float* d, const uint32_t* a, const uint32_t* b) {
    asm volatile("mma.sync.aligned.m16n8k16.row.col.f32.bf16.bf16.f32 "
                 "{%0,%1,%2,%3}, {%4,%5,%6,%7}, {%8,%9}, {%0,%1,%2,%3};"
                 : "+f"(d[0]), "+f"(d[1]), "+f"(d[2]), "+f"(d[3])
                 : "r"(a[0]), "r"(a[1]), "r"(a[2]), "r"(a[3]), "r"(b[0]), "r"(b[1]));
}
__device__ __forceinline__ void cp16(uint32_t dst, const void* src) {
    asm volatile("cp.async.cg.shared.global [%0], [%1], 16;"
                 :: "r"(dst), "l"(src) : "memory");
}
#define CP_COMMIT() asm volatile("cp.async.commit_group;" ::: "memory")
#define CP_WAIT(n)  asm volatile("cp.async.wait_group %0;" :: "n"(n) : "memory")

__device__ __forceinline__ void splitbf(float v, __nv_bfloat16& h, __nv_bfloat16& l) {
    h = __float2bfloat16_rn(v);
    l = __float2bfloat16_rn(v - __bfloat162float(h));
}
__device__ __forceinline__ uint32_t pack2(__nv_bfloat16 a, __nv_bfloat16 b) {
    return (uint32_t)__bfloat16_as_ushort(a) | ((uint32_t)__bfloat16_as_ushort(b) << 16);
}

// ---------------------------------------------------------------------------
// K0: fused splitter for x, Wmix, Wskip -> bf16 hi/lo planes
// ---------------------------------------------------------------------------
#define N4_X   (TT * DIN / 4)
#define N4_WM  (DOUT * DMIX / 4)
#define N4_WS  (DOUT * DIN / 4)
#define N4_ALL (N4_X + N4_WM + N4_WS)

__global__ __launch_bounds__(256) void k_split(const float* __restrict__ x,
                                               const float* __restrict__ Wmix,
                                               const float* __restrict__ Wskip) {
    int i = blockIdx.x * blockDim.x + threadIdx.x;
    if (i >= N4_ALL) return;
    const float* src; __nv_bfloat16 *dH, *dL; int j;
    if (i < N4_X)              { src = x;     dH = g_xH;  dL = g_xL;  j = i; }
    else if (i < N4_X + N4_WM) { src = Wmix;  dH = g_wmH; dL = g_wmL; j = i - N4_X; }
    else                       { src = Wskip; dH = g_wsH; dL = g_wsL; j = i - N4_X - N4_WM; }
    float4 v = ((const float4*)src)[j];
    __nv_bfloat16 h0, l0, h1, l1, h2, l2, h3, l3;
    splitbf(v.x, h0, l0); splitbf(v.y, h1, l1);
    splitbf(v.z, h2, l2); splitbf(v.w, h3, l3);
    ((uint2*)dH)[j] = make_uint2(pack2(h0, h1), pack2(h2, h3));
    ((uint2*)dL)[j] = make_uint2(pack2(l0, l1), pack2(l2, l3));
}

// ---------------------------------------------------------------------------
// K1: pre = rownorm(x @ W_pre^T + b_pre)
// ---------------------------------------------------------------------------
__global__ __launch_bounds__(256) void k_pre(const float* __restrict__ x,
                                             const float* __restrict__ Wp,
                                             const float* __restrict__ bp) {
    __shared__ float xs[32][65];
    __shared__ float ws[32][65];
    __shared__ float nrm[64];
    const int tid = threadIdx.x;
    const int ty = tid >> 4, tx = tid & 15;
    const int row0 = blockIdx.x * 64;

    float acc[4][4];
#pragma unroll
    for (int i = 0; i < 4; i++)
#pragma unroll
        for (int j = 0; j < 4; j++) acc[i][j] = 0.f;

    for (int k0 = 0; k0 < DIN; k0 += 32) {
#pragma unroll
        for (int r = 0; r < 8; r++) {
            int idx = tid + r * 256;
            int m = idx >> 5, k = idx & 31;
            xs[k][m] = x[(size_t)(row0 + m) * DIN + k0 + k];
            ws[k][m] = Wp[(size_t)m * DIN + k0 + k];
        }
        __syncthreads();
#pragma unroll
        for (int kk = 0; kk < 32; kk++) {
            float av[4], bv[4];
#pragma unroll
            for (int i = 0; i < 4; i++) av[i] = xs[kk][ty * 4 + i];
#pragma unroll
            for (int j = 0; j < 4; j++) bv[j] = ws[kk][tx * 4 + j];
#pragma unroll
            for (int i = 0; i < 4; i++)
#pragma unroll
                for (int j = 0; j < 4; j++) acc[i][j] += av[i] * bv[j];
        }
        __syncthreads();
    }
#pragma unroll
    for (int j = 0; j < 4; j++) {
        float b = bp[tx * 4 + j];
#pragma unroll
        for (int i = 0; i < 4; i++) acc[i][j] += b;
    }
    if (tid < 64) nrm[tid] = 0.f;
    __syncthreads();
#pragma unroll
    for (int i = 0; i < 4; i++) {
        float s = 0.f;
#pragma unroll
        for (int j = 0; j < 4; j++) s += acc[i][j] * acc[i][j];
        atomicAdd(&nrm[ty * 4 + i], s);
    }
    __syncthreads();
#pragma unroll
    for (int i = 0; i < 4; i++) {
        float inv = 1.0f / (1e-6f + sqrtf(nrm[ty * 4 + i]));
#pragma unroll
        for (int j = 0; j < 4; j++)
            g_pre[(size_t)(row0 + ty * 4 + i) * MTR + tx * 4 + j] = acc[i][j] * inv;
    }
}

// ---------------------------------------------------------------------------
// K2a: per-chunk local scan from S=0 -> transfer (B, anyStart).  CHUNK=32.
// ---------------------------------------------------------------------------
__global__ __launch_bounds__(256) void k_chunk(const int* __restrict__ start,
                                               const float* __restrict__ a,
                                               const float* __restrict__ bfreq) {
    __shared__ float sp[CHUNK][MTR];
    __shared__ int ss[CHUNK];
    __shared__ int sAny;
    const int tid = threadIdx.x;
    const int ck = blockIdx.x;
    const int t0 = ck * CHUNK;

    for (int idx = tid; idx < CHUNK * MTR; idx += 256)
        sp[idx >> 6][idx & 63] = g_pre[(size_t)(t0 + (idx >> 6)) * MTR + (idx & 63)];
    if (tid < CHUNK) ss[tid] = (start[t0 + tid] != 0);
    if (tid == 0) sAny = 0;
    __syncthreads();
    if (tid < CHUNK && ss[tid]) atomicOr(&sAny, 1);

    const int m = tid >> 2;
    const float gmag = expf(-fabsf(a[m]));
    float gre[4], gim[4], Sre[4], Sim[4];
#pragma unroll
    for (int q = 0; q < 4; q++) {
        int c = ((tid & 3) << 2) + q;
        float sv, cv; sincosf(bfreq[c], &sv, &cv);
        gre[q] = gmag * cv; gim[q] = gmag * sv;
        Sre[q] = 0.f; Sim[q] = 0.f;
    }
    for (int t = 0; t < CHUNK; t++) {
        float p = sp[t][m];
        float keep = ss[t] ? 0.f : 1.f;
#pragma unroll
        for (int q = 0; q < 4; q++) {
            float r  = keep * (gre[q] * Sre[q] - gim[q] * Sim[q]) + p;
            float im = keep * (gre[q] * Sim[q] + gim[q] * Sre[q]);
            Sre[q] = r; Sim[q] = im;
        }
    }
#pragma unroll
    for (int q = 0; q < 4; q++) {
        int ch = tid * 4 + q;
        g_Bre[(size_t)ck * NCH + ch] = Sre[q];
        g_Bim[(size_t)ck * NCH + ch] = Sim[q];
    }
    __syncthreads();
    if (tid == 0) g_any[ck] = sAny;
}

// ---------------------------------------------------------------------------
// K2b: sequential chain, parallel over channels: 32 blocks x 32 channels.
// ---------------------------------------------------------------------------
#define CB 16
__global__ __launch_bounds__(32) void k_chain(const float* __restrict__ s_re0,
                                              const float* __restrict__ s_im0,
                                              const float* __restrict__ a,
                                              const float* __restrict__ bfreq,
                                              float* stateOut) {
    __shared__ float keep_s[NCHUNK];
    const int ch = blockIdx.x * 32 + threadIdx.x;
    const int m = ch >> 4, c = ch & 15;
    for (int idx = threadIdx.x; idx < NCHUNK; idx += 32)
        keep_s[idx] = g_any[idx] ? 0.f : 1.f;
    __syncthreads();

    const float Amag = expf(-(float)CHUNK * fabsf(a[m]));
    float sv, cv; sincosf((float)CHUNK * bfreq[c], &sv, &cv);
    const float Are = Amag * cv, Aim = Amag * sv;
    float Sre = s_re0[ch], Sim = s_im0[ch];

    for (int kb = 0; kb < NCHUNK; kb += CB) {
        float br[CB], bi[CB];
#pragma unroll
        for (int q = 0; q < CB; q++) {
            br[q] = g_Bre[(size_t)(kb + q) * NCH + ch];
            bi[q] = g_Bim[(size_t)(kb + q) * NCH + ch];
        }
#pragma unroll
        for (int q = 0; q < CB; q++) {
            g_cRe[(size_t)(kb + q) * NCH + ch] = Sre;
            g_cIm[(size_t)(kb + q) * NCH + ch] = Sim;
            float keep = keep_s[kb + q];
            float r  = keep * (Are * Sre - Aim * Sim) + br[q];
            float im = keep * (Are * Sim + Aim * Sre) + bi[q];
            Sre = r; Sim = im;
        }
    }
    stateOut[ch]       = Sre;   // planar: re then im
    stateOut[NCH + ch] = Sim;
}

// ---------------------------------------------------------------------------
// K2c: re-scan with true carry, emit zin as bf16 hi/lo planes.  CHUNK=32.
// ---------------------------------------------------------------------------
__global__ __launch_bounds__(256) void k_emit(const int* __restrict__ start,
                                              const float* __restrict__ a,
                                              const float* __restrict__ bfreq) {
    __shared__ float sp[CHUNK][MTR];
    __shared__ int ss[CHUNK];
    const int tid = threadIdx.x;
    const int ck = blockIdx.x;
    const int t0 = ck * CHUNK;

    for (int idx = tid; idx < CHUNK * MTR; idx += 256)
        sp[idx >> 6][idx & 63] = g_pre[(size_t)(t0 + (idx >> 6)) * MTR + (idx & 63)];
    if (tid < CHUNK) ss[tid] = (start[t0 + tid] != 0);
    __syncthreads();

    const int m = tid >> 2;
    const int cg = tid & 3;
    const float gmag = expf(-fabsf(a[m]));
    float gre[4], gim[4], Sre[4], Sim[4];
#pragma unroll
    for (int q = 0; q < 4; q++) {
        int c = cg * 4 + q;
        float sv, cv; sincosf(bfreq[c], &sv, &cv);
        gre[q] = gmag * cv; gim[q] = gmag * sv;
        int ch = m * CCT + c;
        Sre[q] = g_cRe[(size_t)ck * NCH + ch];
        Sim[q] = g_cIm[(size_t)ck * NCH + ch];
    }
    for (int t = 0; t < CHUNK; t++) {
        float p = sp[t][m];
        float keep = ss[t] ? 0.f : 1.f;
#pragma unroll
        for (int q = 0; q < 4; q++) {
            float r  = keep * (gre[q] * Sre[q] - gim[q] * Sim[q]) + p;
            float im = keep * (gre[q] * Sim[q] + gim[q] * Sre[q]);
            Sre[q] = r; Sim[q] = im;
        }
        size_t base = (size_t)(t0 + t) * DMIX + (size_t)m * 32 + cg * 4;
        __nv_bfloat16 h[8], l[8];
#pragma unroll
        for (int q = 0; q < 4; q++) { splitbf(Sre[q], h[q], l[q]); }
#pragma unroll
        for (int q = 0; q < 4; q++) { splitbf(Sim[q], h[4 + q], l[4 + q]); }
        *(uint2*)(g_zinH + base)      = make_uint2(pack2(h[0], h[1]), pack2(h[2], h[3]));
        *(uint2*)(g_zinH + base + 16) = make_uint2(pack2(h[4], h[5]), pack2(h[6], h[7]));
        *(uint2*)(g_zinL + base)      = make_uint2(pack2(l[0], l[1]), pack2(l[2], l[3]));
        *(uint2*)(g_zinL + base + 16) = make_uint2(pack2(l[4], l[5]), pack2(l[6], l[7]));
    }
}

// ---------------------------------------------------------------------------
// K3: out = z_in @ Wmix^T + x @ Wskip^T + biases (bf16-split mma.sync).
// Single-sync cp.async double-buffered mainloop.
// ---------------------------------------------------------------------------
#define ROWB     80
#define OFF_AHI  0
#define OFF_ALO  10240
#define OFF_BHI  20480
#define OFF_BLO  30720
#define STG_SZ   40960
#define SM_TOTAL (1024 + 2 * STG_SZ)
#define KTILES   (KTOT / 32)              // 96
#define MIXTILES (DMIX / 32)              // 64

__global__ __launch_bounds__(256, 2) void k_out_mma(const float* __restrict__ bmix,
                                                    const float* __restrict__ bskip,
                                                    float* __restrict__ out) {
    extern __shared__ char smem[];
    float* bias_s = (float*)smem;
    const uint32_t sb = smem_u32(smem);
    const int tid = threadIdx.x;
    const int lane = tid & 31, wid = tid >> 5;
    const int warp_m = wid & 1, warp_n = wid >> 1;
    const int row0 = blockIdx.y * 128;
    const int col0 = blockIdx.x * 128;

    if (tid < 128) bias_s[tid] = bmix[col0 + tid] + bskip[col0 + tid];

    float acc[4][4][4];
#pragma unroll
    for (int i = 0; i < 4; i++)
#pragma unroll
        for (int j = 0; j < 4; j++)
#pragma unroll
            for (int q = 0; q < 4; q++) acc[i][j][q] = 0.f;

    // hoisted cp.async geometry: per r-chunk the row (rw) and 16B slot (c16)
    const int rw0  = tid >> 2;            // r = 0 chunk
    const int rw1  = (tid + 256) >> 2;    // r = 1 chunk
    const int c16a = tid & 3;
    const uint32_t soff0 = (uint32_t)rw0 * ROWB + (uint32_t)c16a * 16;
    const uint32_t soff1 = (uint32_t)rw1 * ROWB + (uint32_t)c16a * 16;

    auto issue_cp = [&](int kt, uint32_t stg) {
        const bool mix = kt < MIXTILES;
        const __nv_bfloat16* aH = mix ? g_zinH : g_xH;
        const __nv_bfloat16* aL = mix ? g_zinL : g_xL;
        const __nv_bfloat16* bH = mix ? g_wmH : g_wsH;
        const __nv_bfloat16* bL = mix ? g_wmL : g_wsL;
        const int ldx = mix ? DMIX : DIN;
        const int kk0 = (mix ? kt * 32 : (kt - MIXTILES) * 32) + c16a * 8;
        size_t gA0 = (size_t)(row0 + rw0) * ldx + kk0;
        size_t gB0 = (size_t)(col0 + rw0) * ldx + kk0;
        size_t gA1 = (size_t)(row0 + rw1) * ldx + kk0;
        size_t gB1 = (size_t)(col0 + rw1) * ldx + kk0;
        cp16(stg + OFF_AHI + soff0, aH + gA0);
        cp16(stg + OFF_ALO + soff0, aL + gA0);
        cp16(stg + OFF_BHI + soff0, bH + gB0);
        cp16(stg + OFF_BLO + soff0, bL + gB0);
        cp16(stg + OFF_AHI + soff1, aH + gA1);
        cp16(stg + OFF_ALO + soff1, aL + gA1);
        cp16(stg + OFF_BHI + soff1, bH + gB1);
        cp16(stg + OFF_BLO + soff1, bL + gB1);
        CP_COMMIT();
    };

    issue_cp(0, sb + 1024);

    const uint32_t aoff = (uint32_t)(warp_m * 64 + (lane & 15)) * ROWB
                        + ((lane >> 4) & 1) * 16;
    const uint32_t boff = (uint32_t)(warp_n * 32 + (lane & 7) + (((lane >> 4) & 1) << 3)) * ROWB
                        + ((lane >> 3) & 1) * 16;

    for (int kt = 0; kt < KTILES; kt++) {
        const uint32_t stg = sb + 1024 + (uint32_t)(kt & 1) * STG_SZ;
        CP_WAIT(0);
        __syncthreads();
        if (kt + 1 < KTILES)
            issue_cp(kt + 1, sb + 1024 + (uint32_t)((kt + 1) & 1) * STG_SZ);

#pragma unroll
        for (int s = 0; s < 2; s++) {
            const uint32_t ks = s * 32;
            uint32_t bh[8], bl[8], afr[16];
            ldsm4(bh + 0, stg + OFF_BHI + boff + ks);
            ldsm4(bh + 4, stg + OFF_BHI + boff + 16 * ROWB + ks);
            ldsm4(bl + 0, stg + OFF_BLO + boff + ks);
            ldsm4(bl + 4, stg + OFF_BLO + boff + 16 * ROWB + ks);
#pragma unroll
            for (int i = 0; i < 4; i++)
                ldsm4(afr + i * 4, stg + OFF_AHI + aoff + (uint32_t)i * 16 * ROWB + ks);
#pragma unroll
            for (int i = 0; i < 4; i++)
#pragma unroll
                for (int j = 0; j < 4; j++)
                    mma_bf16(acc[i][j], afr + i * 4, bh + j * 2);
#pragma unroll
            for (int i = 0; i < 4; i++)
#pragma unroll
                for (int j = 0; j < 4; j++)
                    mma_bf16(acc[i][j], afr + i * 4, bl + j * 2);
#pragma unroll
            for (int i = 0; i < 4; i++)
                ldsm4(afr + i * 4, stg + OFF_ALO + aoff + (uint32_t)i * 16 * ROWB + ks);
#pragma unroll
            for (int i = 0; i < 4; i++)
#pragma unroll
                for (int j = 0; j < 4; j++)
                    mma_bf16(acc[i][j], afr + i * 4, bh + j * 2);
        }
    }

    const int r_base = row0 + warp_m * 64 + (lane >> 2);
    const int c_base = warp_n * 32 + (lane & 3) * 2;
#pragma unroll
    for (int i = 0; i < 4; i++) {
#pragma unroll
        for (int j = 0; j < 4; j++) {
            int r = r_base + i * 16;
            int c = c_base + j * 8;
            float b0 = bias_s[c], b1 = bias_s[c + 1];
            float2 v0 = make_float2(acc[i][j][0] + b0, acc[i][j][1] + b1);
            float2 v1 = make_float2(acc[i][j][2] + b0, acc[i][j][3] + b1);
            *(float2*)(out + (size_t)r * DOUT + col0 + c) = v0;
            *(float2*)(out + (size_t)(r + 8) * DOUT + col0 + c) = v1;
        }
    }
}

// ---------------------------------------------------------------------------
// Launch
// ---------------------------------------------------------------------------
extern "C" void kernel_launch(void* const* d_in, const int* in_sizes, int n_in,
                              void* d_out, int out_size) {
    const float* x     = (const float*)d_in[0];
    const float* s_re  = (const float*)d_in[1];
    const float* s_im  = (const float*)d_in[2];
    const int*   start = (const int*)d_in[3];
    const float* Wpre  = (const float*)d_in[5];
    const float* bpre  = (const float*)d_in[6];
    const float* Wskip = (const float*)d_in[7];
    const float* bskip = (const float*)d_in[8];
    const float* Wmix  = (const float*)d_in[9];
    const float* bmix  = (const float*)d_in[10];
    const float* a     = (const float*)d_in[11];
    const float* bf    = (const float*)d_in[12];
    float* out = (float*)d_out;
    float* stateOut = out + (size_t)TT * DOUT;

    cudaFuncSetAttribute(k_out_mma, cudaFuncAttributeMaxDynamicSharedMemorySize, SM_TOTAL);

    k_split<<<(N4_ALL + 255) / 256, 256>>>(x, Wmix, Wskip);
    k_pre<<<TT / 64, 256>>>(x, Wpre, bpre);
    k_chunk<<<NCHUNK, 256>>>(start, a, bf);
    k_chain<<<NCH / 32, 32>>>(s_re, s_im, a, bf, stateOut);
    k_emit<<<NCHUNK, 256>>>(start, a, bf);
    dim3 g3(DOUT / 128, TT / 128);
    k_out_mma<<<g3, 256, SM_TOTAL>>>(bmix, bskip, out);
}

// round 10
// speedup vs baseline: 2.7529x; 1.1381x over previous
#include <cuda_runtime.h>
#include <cuda_bf16.h>
#include <math.h>
#include <stdint.h>

#define TT      8192
#define DIN     1024
#define DOUT    1024
#define MTR     64
#define CCT     16
#define NCH     1024
#define CHUNK   32
#define NCHUNK  256           // TT/CHUNK
#define DMIX    2048
#define KTOT    (DMIX + DIN)  // 3072

// Scratch
__device__ float g_pre[TT * MTR];
__device__ float g_Bre[NCHUNK * NCH];
__device__ float g_Bim[NCHUNK * NCH];
__device__ float g_cRe[NCHUNK * NCH];
__device__ float g_cIm[NCHUNK * NCH];
__device__ int   g_any[NCHUNK];
// bf16 hi/lo planes for the big GEMM
__device__ __nv_bfloat16 g_zinH[TT * DMIX];
__device__ __nv_bfloat16 g_zinL[TT * DMIX];
__device__ __nv_bfloat16 g_xH[TT * DIN];
__device__ __nv_bfloat16 g_xL[TT * DIN];
__device__ __nv_bfloat16 g_wmH[DOUT * DMIX];
__device__ __nv_bfloat16 g_wmL[DOUT * DMIX];
__device__ __nv_bfloat16 g_wsH[DOUT * DIN];
__device__ __nv_bfloat16 g_wsL[DOUT * DIN];

// ---------------------------------------------------------------------------
// helpers
// ---------------------------------------------------------------------------
__device__ __forceinline__ uint32_t smem_u32(const void* p) {
    uint32_t a;
    asm("{ .reg .u64 t; cvta.to.shared.u64 t, %1; cvt.u32.u64 %0, t; }" : "=r"(a) : "l"(p));
    return a;
}
__device__ __forceinline__ void ldsm4(uint32_t* r, uint32_t addr) {
    asm volatile("ldmatrix.sync.aligned.m8n8.x4.shared.b16 {%0,%1,%2,%3}, [%4];"
                 : "=r"(r[0]), "=r"(r[1]), "=r"(r[2]), "=r"(r[3]) : "r"(addr));
}
__device__ __forceinline__ void mma_bf16(float* d, const uint32_t* a, const uint32_t* b) {
    asm volatile("mma.sync.aligned.m16n8k16.row.col.f32.bf16.bf16.f32 "
                 "{%0,%1,%2,%3}, {%4,%5,%6,%7}, {%8,%9}, {%0,%1,%2,%3};"
                 : "+f"(d[0]), "+f"(d[1]), "+f"(d[2]), "+f"(d[3])
                 : "r"(a[0]), "r"(a[1]), "r"(a[2]), "r"(a[3]), "r"(b[0]), "r"(b[1]));
}
__device__ __forceinline__ void cp16(uint32_t dst, const void* src) {
    asm volatile("cp.async.cg.shared.global [%0], [%1], 16;"
                 :: "r"(dst), "l"(src) : "memory");
}
#define CP_COMMIT() asm volatile("cp.async.commit_group;" ::: "memory")
#define CP_WAIT(n)  asm volatile("cp.async.wait_group %0;" :: "n"(n) : "memory")

__device__ __forceinline__ void splitbf(float v, __nv_bfloat16& h, __nv_bfloat16& l) {
    h = __float2bfloat16_rn(v);
    l = __float2bfloat16_rn(v - __bfloat162float(h));
}
__device__ __forceinline__ uint32_t pack2(__nv_bfloat16 a, __nv_bfloat16 b) {
    return (uint32_t)__bfloat16_as_ushort(a) | ((uint32_t)__bfloat16_as_ushort(b) << 16);
}

// ---------------------------------------------------------------------------
// K0: fused splitter for x, Wmix, Wskip -> bf16 hi/lo planes
// ---------------------------------------------------------------------------
#define N4_X   (TT * DIN / 4)
#define N4_WM  (DOUT * DMIX / 4)
#define N4_WS  (DOUT * DIN / 4)
#define N4_ALL (N4_X + N4_WM + N4_WS)

__global__ __launch_bounds__(256) void k_split(const float* __restrict__ x,
                                               const float* __restrict__ Wmix,
                                               const float* __restrict__ Wskip) {
    int i = blockIdx.x * blockDim.x + threadIdx.x;
    if (i >= N4_ALL) return;
    const float* src; __nv_bfloat16 *dH, *dL; int j;
    if (i < N4_X)              { src = x;     dH = g_xH;  dL = g_xL;  j = i; }
    else if (i < N4_X + N4_WM) { src = Wmix;  dH = g_wmH; dL = g_wmL; j = i - N4_X; }
    else                       { src = Wskip; dH = g_wsH; dL = g_wsL; j = i - N4_X - N4_WM; }
    float4 v = ((const float4*)src)[j];
    __nv_bfloat16 h0, l0, h1, l1, h2, l2, h3, l3;
    splitbf(v.x, h0, l0); splitbf(v.y, h1, l1);
    splitbf(v.z, h2, l2); splitbf(v.w, h3, l3);
    ((uint2*)dH)[j] = make_uint2(pack2(h0, h1), pack2(h2, h3));
    ((uint2*)dL)[j] = make_uint2(pack2(l0, l1), pack2(l2, l3));
}

// ---------------------------------------------------------------------------
// K1: pre = rownorm(x @ W_pre^T + b_pre)
// ---------------------------------------------------------------------------
__global__ __launch_bounds__(256) void k_pre(const float* __restrict__ x,
                                             const float* __restrict__ Wp,
                                             const float* __restrict__ bp) {
    __shared__ float xs[32][65];
    __shared__ float ws[32][65];
    __shared__ float nrm[64];
    const int tid = threadIdx.x;
    const int ty = tid >> 4, tx = tid & 15;
    const int row0 = blockIdx.x * 64;

    float acc[4][4];
#pragma unroll
    for (int i = 0; i < 4; i++)
#pragma unroll
        for (int j = 0; j < 4; j++) acc[i][j] = 0.f;

    for (int k0 = 0; k0 < DIN; k0 += 32) {
#pragma unroll
        for (int r = 0; r < 8; r++) {
            int idx = tid + r * 256;
            int m = idx >> 5, k = idx & 31;
            xs[k][m] = x[(size_t)(row0 + m) * DIN + k0 + k];
            ws[k][m] = Wp[(size_t)m * DIN + k0 + k];
        }
        __syncthreads();
#pragma unroll
        for (int kk = 0; kk < 32; kk++) {
            float av[4], bv[4];
#pragma unroll
            for (int i = 0; i < 4; i++) av[i] = xs[kk][ty * 4 + i];
#pragma unroll
            for (int j = 0; j < 4; j++) bv[j] = ws[kk][tx * 4 + j];
#pragma unroll
            for (int i = 0; i < 4; i++)
#pragma unroll
                for (int j = 0; j < 4; j++) acc[i][j] += av[i] * bv[j];
        }
        __syncthreads();
    }
#pragma unroll
    for (int j = 0; j < 4; j++) {
        float b = bp[tx * 4 + j];
#pragma unroll
        for (int i = 0; i < 4; i++) acc[i][j] += b;
    }
    if (tid < 64) nrm[tid] = 0.f;
    __syncthreads();
#pragma unroll
    for (int i = 0; i < 4; i++) {
        float s = 0.f;
#pragma unroll
        for (int j = 0; j < 4; j++) s += acc[i][j] * acc[i][j];
        atomicAdd(&nrm[ty * 4 + i], s);
    }
    __syncthreads();
#pragma unroll
    for (int i = 0; i < 4; i++) {
        float inv = 1.0f / (1e-6f + sqrtf(nrm[ty * 4 + i]));
#pragma unroll
        for (int j = 0; j < 4; j++)
            g_pre[(size_t)(row0 + ty * 4 + i) * MTR + tx * 4 + j] = acc[i][j] * inv;
    }
}

// ---------------------------------------------------------------------------
// K2a: per-chunk local scan from S=0 -> transfer (B, anyStart).  CHUNK=32.
// ---------------------------------------------------------------------------
__global__ __launch_bounds__(256) void k_chunk(const int* __restrict__ start,
                                               const float* __restrict__ a,
                                               const float* __restrict__ bfreq) {
    __shared__ float sp[CHUNK][MTR];
    __shared__ int ss[CHUNK];
    __shared__ int sAny;
    const int tid = threadIdx.x;
    const int ck = blockIdx.x;
    const int t0 = ck * CHUNK;

    for (int idx = tid; idx < CHUNK * MTR; idx += 256)
        sp[idx >> 6][idx & 63] = g_pre[(size_t)(t0 + (idx >> 6)) * MTR + (idx & 63)];
    if (tid < CHUNK) ss[tid] = (start[t0 + tid] != 0);
    if (tid == 0) sAny = 0;
    __syncthreads();
    if (tid < CHUNK && ss[tid]) atomicOr(&sAny, 1);

    const int m = tid >> 2;
    const float gmag = expf(-fabsf(a[m]));
    float gre[4], gim[4], Sre[4], Sim[4];
#pragma unroll
    for (int q = 0; q < 4; q++) {
        int c = ((tid & 3) << 2) + q;
        float sv, cv; sincosf(bfreq[c], &sv, &cv);
        gre[q] = gmag * cv; gim[q] = gmag * sv;
        Sre[q] = 0.f; Sim[q] = 0.f;
    }
    for (int t = 0; t < CHUNK; t++) {
        float p = sp[t][m];
        float keep = ss[t] ? 0.f : 1.f;
#pragma unroll
        for (int q = 0; q < 4; q++) {
            float r  = keep * (gre[q] * Sre[q] - gim[q] * Sim[q]) + p;
            float im = keep * (gre[q] * Sim[q] + gim[q] * Sre[q]);
            Sre[q] = r; Sim[q] = im;
        }
    }
#pragma unroll
    for (int q = 0; q < 4; q++) {
        int ch = tid * 4 + q;
        g_Bre[(size_t)ck * NCH + ch] = Sre[q];
        g_Bim[(size_t)ck * NCH + ch] = Sim[q];
    }
    __syncthreads();
    if (tid == 0) g_any[ck] = sAny;
}

// ---------------------------------------------------------------------------
// K2b: sequential chain, parallel over channels: 32 blocks x 32 channels.
// ---------------------------------------------------------------------------
#define CB 16
__global__ __launch_bounds__(32) void k_chain(const float* __restrict__ s_re0,
                                              const float* __restrict__ s_im0,
                                              const float* __restrict__ a,
                                              const float* __restrict__ bfreq,
                                              float* stateOut) {
    __shared__ float keep_s[NCHUNK];
    const int ch = blockIdx.x * 32 + threadIdx.x;
    const int m = ch >> 4, c = ch & 15;
    for (int idx = threadIdx.x; idx < NCHUNK; idx += 32)
        keep_s[idx] = g_any[idx] ? 0.f : 1.f;
    __syncthreads();

    const float Amag = expf(-(float)CHUNK * fabsf(a[m]));
    float sv, cv; sincosf((float)CHUNK * bfreq[c], &sv, &cv);
    const float Are = Amag * cv, Aim = Amag * sv;
    float Sre = s_re0[ch], Sim = s_im0[ch];

    for (int kb = 0; kb < NCHUNK; kb += CB) {
        float br[CB], bi[CB];
#pragma unroll
        for (int q = 0; q < CB; q++) {
            br[q] = g_Bre[(size_t)(kb + q) * NCH + ch];
            bi[q] = g_Bim[(size_t)(kb + q) * NCH + ch];
        }
#pragma unroll
        for (int q = 0; q < CB; q++) {
            g_cRe[(size_t)(kb + q) * NCH + ch] = Sre;
            g_cIm[(size_t)(kb + q) * NCH + ch] = Sim;
            float keep = keep_s[kb + q];
            float r  = keep * (Are * Sre - Aim * Sim) + br[q];
            float im = keep * (Are * Sim + Aim * Sre) + bi[q];
            Sre = r; Sim = im;
        }
    }
    stateOut[ch]       = Sre;   // planar: re then im
    stateOut[NCH + ch] = Sim;
}

// ---------------------------------------------------------------------------
// K2c: re-scan with true carry, emit zin as bf16 hi/lo planes.  CHUNK=32.
// ---------------------------------------------------------------------------
__global__ __launch_bounds__(256) void k_emit(const int* __restrict__ start,
                                              const float* __restrict__ a,
                                              const float* __restrict__ bfreq) {
    __shared__ float sp[CHUNK][MTR];
    __shared__ int ss[CHUNK];
    const int tid = threadIdx.x;
    const int ck = blockIdx.x;
    const int t0 = ck * CHUNK;

    for (int idx = tid; idx < CHUNK * MTR; idx += 256)
        sp[idx >> 6][idx & 63] = g_pre[(size_t)(t0 + (idx >> 6)) * MTR + (idx & 63)];
    if (tid < CHUNK) ss[tid] = (start[t0 + tid] != 0);
    __syncthreads();

    const int m = tid >> 2;
    const int cg = tid & 3;
    const float gmag = expf(-fabsf(a[m]));
    float gre[4], gim[4], Sre[4], Sim[4];
#pragma unroll
    for (int q = 0; q < 4; q++) {
        int c = cg * 4 + q;
        float sv, cv; sincosf(bfreq[c], &sv, &cv);
        gre[q] = gmag * cv; gim[q] = gmag * sv;
        int ch = m * CCT + c;
        Sre[q] = g_cRe[(size_t)ck * NCH + ch];
        Sim[q] = g_cIm[(size_t)ck * NCH + ch];
    }
    for (int t = 0; t < CHUNK; t++) {
        float p = sp[t][m];
        float keep = ss[t] ? 0.f : 1.f;
#pragma unroll
        for (int q = 0; q < 4; q++) {
            float r  = keep * (gre[q] * Sre[q] - gim[q] * Sim[q]) + p;
            float im = keep * (gre[q] * Sim[q] + gim[q] * Sre[q]);
            Sre[q] = r; Sim[q] = im;
        }
        size_t base = (size_t)(t0 + t) * DMIX + (size_t)m * 32 + cg * 4;
        __nv_bfloat16 h[8], l[8];
#pragma unroll
        for (int q = 0; q < 4; q++) { splitbf(Sre[q], h[q], l[q]); }
#pragma unroll
        for (int q = 0; q < 4; q++) { splitbf(Sim[q], h[4 + q], l[4 + q]); }
        *(uint2*)(g_zinH + base)      = make_uint2(pack2(h[0], h[1]), pack2(h[2], h[3]));
        *(uint2*)(g_zinH + base + 16) = make_uint2(pack2(h[4], h[5]), pack2(h[6], h[7]));
        *(uint2*)(g_zinL + base)      = make_uint2(pack2(l[0], l[1]), pack2(l[2], l[3]));
        *(uint2*)(g_zinL + base + 16) = make_uint2(pack2(l[4], l[5]), pack2(l[6], l[7]));
    }
}

// ---------------------------------------------------------------------------
// K3: out = z_in @ Wmix^T + x @ Wskip^T + biases (bf16-split mma.sync).
// CTA 128x128, 4 warps (2x2), warp tile 64x64.  XOR-swizzled 64B rows:
// physical 16B-chunk = c ^ ((row>>1)&3)  -> ldmatrix AND cp.async stores
// both bank-conflict-free; swizzle key invariant under row+=16.
// ---------------------------------------------------------------------------
#define OFF_AHI  0
#define OFF_ALO  8192
#define OFF_BHI  16384
#define OFF_BLO  24576
#define STG_SZ   32768
#define SM_TOTAL (1024 + 2 * STG_SZ)      // 66560
#define KTILES   (KTOT / 32)              // 96
#define MIXTILES (DMIX / 32)              // 64

__device__ __forceinline__ uint32_t swz(uint32_t row, uint32_t chunk) {
    return row * 64u + ((chunk ^ ((row >> 1) & 3u)) << 4);
}

__global__ __launch_bounds__(128, 2) void k_out_mma(const float* __restrict__ bmix,
                                                    const float* __restrict__ bskip,
                                                    float* __restrict__ out) {
    extern __shared__ char smem[];
    float* bias_s = (float*)smem;
    const uint32_t sb = smem_u32(smem);
    const int tid = threadIdx.x;
    const int lane = tid & 31, wid = tid >> 5;
    const int warp_m = wid & 1, warp_n = wid >> 1;     // 2x2 warps
    const int row0 = blockIdx.y * 128;
    const int col0 = blockIdx.x * 128;

    bias_s[tid] = bmix[col0 + tid] + bskip[col0 + tid];

    float acc[4][8][4];
#pragma unroll
    for (int i = 0; i < 4; i++)
#pragma unroll
        for (int j = 0; j < 8; j++)
#pragma unroll
            for (int q = 0; q < 4; q++) acc[i][j][q] = 0.f;

    // cp.async geometry: 512 16B-chunks per array, 128 threads -> 4 each
    const int rwv[4] = { tid >> 2, (tid + 128) >> 2, (tid + 256) >> 2, (tid + 384) >> 2 };
    const int c16a = tid & 3;
    uint32_t soffv[4];
#pragma unroll
    for (int r = 0; r < 4; r++) soffv[r] = swz((uint32_t)rwv[r], (uint32_t)c16a);

    auto issue_cp = [&](int kt, uint32_t stg) {
        const bool mix = kt < MIXTILES;
        const __nv_bfloat16* aH = mix ? g_zinH : g_xH;
        const __nv_bfloat16* aL = mix ? g_zinL : g_xL;
        const __nv_bfloat16* bH = mix ? g_wmH : g_wsH;
        const __nv_bfloat16* bL = mix ? g_wmL : g_wsL;
        const int ldx = mix ? DMIX : DIN;
        const int kk0 = (mix ? kt * 32 : (kt - MIXTILES) * 32) + c16a * 8;
#pragma unroll
        for (int r = 0; r < 4; r++) {
            size_t gA = (size_t)(row0 + rwv[r]) * ldx + kk0;
            size_t gB = (size_t)(col0 + rwv[r]) * ldx + kk0;
            cp16(stg + OFF_AHI + soffv[r], aH + gA);
            cp16(stg + OFF_ALO + soffv[r], aL + gA);
            cp16(stg + OFF_BHI + soffv[r], bH + gB);
            cp16(stg + OFF_BLO + soffv[r], bL + gB);
        }
        CP_COMMIT();
    };

    issue_cp(0, sb + 1024);

    // ldmatrix lane geometry (swizzle key invariant under row += 16)
    const uint32_t aRow = (uint32_t)(warp_m * 64 + (lane & 15));
    const uint32_t aHi  = (lane >> 4) & 1;
    const uint32_t keyA = (aRow >> 1) & 3;
    const uint32_t bRow = (uint32_t)(warp_n * 64 + (lane & 7) + (((lane >> 4) & 1) << 3));
    const uint32_t bHi  = (lane >> 3) & 1;
    const uint32_t keyB = (bRow >> 1) & 3;

    for (int kt = 0; kt < KTILES; kt++) {
        const uint32_t stg = sb + 1024 + (uint32_t)(kt & 1) * STG_SZ;
        CP_WAIT(0);
        __syncthreads();
        if (kt + 1 < KTILES)
            issue_cp(kt + 1, sb + 1024 + (uint32_t)((kt + 1) & 1) * STG_SZ);

#pragma unroll
        for (int s = 0; s < 2; s++) {
            const uint32_t cA = ((2u * s + aHi) ^ keyA) << 4;
            const uint32_t cB = ((2u * s + bHi) ^ keyB) << 4;
            const uint32_t aAddr = stg + OFF_AHI + aRow * 64 + cA;
            const uint32_t bAddr = stg + OFF_BHI + bRow * 64 + cB;
            uint32_t bh[16], bl[16], afr[16];
#pragma unroll
            for (int jj = 0; jj < 4; jj++)
                ldsm4(bh + jj * 4, bAddr + (uint32_t)jj * 1024);
#pragma unroll
            for (int jj = 0; jj < 4; jj++)
                ldsm4(bl + jj * 4, bAddr + (OFF_BLO - OFF_BHI) + (uint32_t)jj * 1024);
#pragma unroll
            for (int i = 0; i < 4; i++)
                ldsm4(afr + i * 4, aAddr + (uint32_t)i * 1024);
#pragma unroll
            for (int i = 0; i < 4; i++)
#pragma unroll
                for (int j = 0; j < 8; j++)
                    mma_bf16(acc[i][j], afr + i * 4, bh + j * 2);
#pragma unroll
            for (int i = 0; i < 4; i++)
#pragma unroll
                for (int j = 0; j < 8; j++)
                    mma_bf16(acc[i][j], afr + i * 4, bl + j * 2);
#pragma unroll
            for (int i = 0; i < 4; i++)
                ldsm4(afr + i * 4, aAddr + (OFF_ALO - OFF_AHI) + (uint32_t)i * 1024);
#pragma unroll
            for (int i = 0; i < 4; i++)
#pragma unroll
                for (int j = 0; j < 8; j++)
                    mma_bf16(acc[i][j], afr + i * 4, bh + j * 2);
        }
    }

    const int r_base = row0 + warp_m * 64 + (lane >> 2);
    const int c_base = warp_n * 64 + (lane & 3) * 2;
#pragma unroll
    for (int i = 0; i < 4; i++) {
#pragma unroll
        for (int j = 0; j < 8; j++) {
            int r = r_base + i * 16;
            int c = c_base + j * 8;
            float b0 = bias_s[c], b1 = bias_s[c + 1];
            float2 v0 = make_float2(acc[i][j][0] + b0, acc[i][j][1] + b1);
            float2 v1 = make_float2(acc[i][j][2] + b0, acc[i][j][3] + b1);
            *(float2*)(out + (size_t)r * DOUT + col0 + c) = v0;
            *(float2*)(out + (size_t)(r + 8) * DOUT + col0 + c) = v1;
        }
    }
}

// ---------------------------------------------------------------------------
// Launch
// ---------------------------------------------------------------------------
extern "C" void kernel_launch(void* const* d_in, const int* in_sizes, int n_in,
                              void* d_out, int out_size) {
    const float* x     = (const float*)d_in[0];
    const float* s_re  = (const float*)d_in[1];
    const float* s_im  = (const float*)d_in[2];
    const int*   start = (const int*)d_in[3];
    const float* Wpre  = (const float*)d_in[5];
    const float* bpre  = (const float*)d_in[6];
    const float* Wskip = (const float*)d_in[7];
    const float* bskip = (const float*)d_in[8];
    const float* Wmix  = (const float*)d_in[9];
    const float* bmix  = (const float*)d_in[10];
    const float* a     = (const float*)d_in[11];
    const float* bf    = (const float*)d_in[12];
    float* out = (float*)d_out;
    float* stateOut = out + (size_t)TT * DOUT;

    cudaFuncSetAttribute(k_out_mma, cudaFuncAttributeMaxDynamicSharedMemorySize, SM_TOTAL);

    k_split<<<(N4_ALL + 255) / 256, 256>>>(x, Wmix, Wskip);
    k_pre<<<TT / 64, 256>>>(x, Wpre, bpre);
    k_chunk<<<NCHUNK, 256>>>(start, a, bf);
    k_chain<<<NCH / 32, 32>>>(s_re, s_im, a, bf, stateOut);
    k_emit<<<NCHUNK, 256>>>(start, a, bf);
    dim3 g3(DOUT / 128, TT / 128);
    k_out_mma<<<g3, 128, SM_TOTAL>>>(bmix, bskip, out);
}

// round 11
// speedup vs baseline: 3.6220x; 1.3157x over previous
#include <cuda_runtime.h>
#include <cuda_fp16.h>
#include <math.h>
#include <stdint.h>

#define TT      8192
#define DIN     1024
#define DOUT    1024
#define MTR     64
#define CCT     16
#define NCH     1024
#define CHUNK   32
#define NCHUNK  256           // TT/CHUNK
#define DMIX    2048
#define KTOT    (DMIX + DIN)  // 3072

// Scratch
__device__ float g_pre[TT * MTR];
__device__ float g_Bre[NCHUNK * NCH];
__device__ float g_Bim[NCHUNK * NCH];
__device__ float g_cRe[NCHUNK * NCH];
__device__ float g_cIm[NCHUNK * NCH];
__device__ int   g_any[NCHUNK];
// fp16 planes for the big GEMM: activations single plane, weights hi+lo
__device__ __half g_zin16[TT * DMIX];
__device__ __half g_x16[TT * DIN];
__device__ __half g_wmH[DOUT * DMIX];
__device__ __half g_wmL[DOUT * DMIX];
__device__ __half g_wsH[DOUT * DIN];
__device__ __half g_wsL[DOUT * DIN];

// ---------------------------------------------------------------------------
// helpers
// ---------------------------------------------------------------------------
__device__ __forceinline__ uint32_t smem_u32(const void* p) {
    uint32_t a;
    asm("{ .reg .u64 t; cvta.to.shared.u64 t, %1; cvt.u32.u64 %0, t; }" : "=r"(a) : "l"(p));
    return a;
}
__device__ __forceinline__ void ldsm4(uint32_t* r, uint32_t addr) {
    asm volatile("ldmatrix.sync.aligned.m8n8.x4.shared.b16 {%0,%1,%2,%3}, [%4];"
                 : "=r"(r[0]), "=r"(r[1]), "=r"(r[2]), "=r"(r[3]) : "r"(addr));
}
__device__ __forceinline__ void mma_f16(float* d, const uint32_t* a, const uint32_t* b) {
    asm volatile("mma.sync.aligned.m16n8k16.row.col.f32.f16.f16.f32 "
                 "{%0,%1,%2,%3}, {%4,%5,%6,%7}, {%8,%9}, {%0,%1,%2,%3};"
                 : "+f"(d[0]), "+f"(d[1]), "+f"(d[2]), "+f"(d[3])
                 : "r"(a[0]), "r"(a[1]), "r"(a[2]), "r"(a[3]), "r"(b[0]), "r"(b[1]));
}
__device__ __forceinline__ void cp16(uint32_t dst, const void* src) {
    asm volatile("cp.async.cg.shared.global [%0], [%1], 16;"
                 :: "r"(dst), "l"(src) : "memory");
}
#define CP_COMMIT() asm volatile("cp.async.commit_group;" ::: "memory")
#define CP_WAIT(n)  asm volatile("cp.async.wait_group %0;" :: "n"(n) : "memory")

__device__ __forceinline__ void splitf16(float v, __half& h, __half& l) {
    h = __float2half_rn(v);
    l = __float2half_rn(v - __half2float(h));
}
__device__ __forceinline__ uint32_t pack2h(__half a, __half b) {
    return (uint32_t)__half_as_ushort(a) | ((uint32_t)__half_as_ushort(b) << 16);
}

// ---------------------------------------------------------------------------
// K0: x -> fp16 plane; Wmix/Wskip -> fp16 hi+lo planes
// ---------------------------------------------------------------------------
#define N4_X   (TT * DIN / 4)
#define N4_WM  (DOUT * DMIX / 4)
#define N4_WS  (DOUT * DIN / 4)
#define N4_ALL (N4_X + N4_WM + N4_WS)

__global__ __launch_bounds__(256) void k_split(const float* __restrict__ x,
                                               const float* __restrict__ Wmix,
                                               const float* __restrict__ Wskip) {
    int i = blockIdx.x * blockDim.x + threadIdx.x;
    if (i >= N4_ALL) return;
    if (i < N4_X) {
        float4 v = ((const float4*)x)[i];
        ((uint2*)g_x16)[i] = make_uint2(
            pack2h(__float2half_rn(v.x), __float2half_rn(v.y)),
            pack2h(__float2half_rn(v.z), __float2half_rn(v.w)));
        return;
    }
    const float* src; __half *dH, *dL; int j;
    if (i < N4_X + N4_WM) { src = Wmix;  dH = g_wmH; dL = g_wmL; j = i - N4_X; }
    else                  { src = Wskip; dH = g_wsH; dL = g_wsL; j = i - N4_X - N4_WM; }
    float4 v = ((const float4*)src)[j];
    __half h0, l0, h1, l1, h2, l2, h3, l3;
    splitf16(v.x, h0, l0); splitf16(v.y, h1, l1);
    splitf16(v.z, h2, l2); splitf16(v.w, h3, l3);
    ((uint2*)dH)[j] = make_uint2(pack2h(h0, h1), pack2h(h2, h3));
    ((uint2*)dL)[j] = make_uint2(pack2h(l0, l1), pack2h(l2, l3));
}

// ---------------------------------------------------------------------------
// K1: pre = rownorm(x @ W_pre^T + b_pre)
// ---------------------------------------------------------------------------
__global__ __launch_bounds__(256) void k_pre(const float* __restrict__ x,
                                             const float* __restrict__ Wp,
                                             const float* __restrict__ bp) {
    __shared__ float xs[32][65];
    __shared__ float ws[32][65];
    __shared__ float nrm[64];
    const int tid = threadIdx.x;
    const int ty = tid >> 4, tx = tid & 15;
    const int row0 = blockIdx.x * 64;

    float acc[4][4];
#pragma unroll
    for (int i = 0; i < 4; i++)
#pragma unroll
        for (int j = 0; j < 4; j++) acc[i][j] = 0.f;

    for (int k0 = 0; k0 < DIN; k0 += 32) {
#pragma unroll
        for (int r = 0; r < 8; r++) {
            int idx = tid + r * 256;
            int m = idx >> 5, k = idx & 31;
            xs[k][m] = x[(size_t)(row0 + m) * DIN + k0 + k];
            ws[k][m] = Wp[(size_t)m * DIN + k0 + k];
        }
        __syncthreads();
#pragma unroll
        for (int kk = 0; kk < 32; kk++) {
            float av[4], bv[4];
#pragma unroll
            for (int i = 0; i < 4; i++) av[i] = xs[kk][ty * 4 + i];
#pragma unroll
            for (int j = 0; j < 4; j++) bv[j] = ws[kk][tx * 4 + j];
#pragma unroll
            for (int i = 0; i < 4; i++)
#pragma unroll
                for (int j = 0; j < 4; j++) acc[i][j] += av[i] * bv[j];
        }
        __syncthreads();
    }
#pragma unroll
    for (int j = 0; j < 4; j++) {
        float b = bp[tx * 4 + j];
#pragma unroll
        for (int i = 0; i < 4; i++) acc[i][j] += b;
    }
    if (tid < 64) nrm[tid] = 0.f;
    __syncthreads();
#pragma unroll
    for (int i = 0; i < 4; i++) {
        float s = 0.f;
#pragma unroll
        for (int j = 0; j < 4; j++) s += acc[i][j] * acc[i][j];
        atomicAdd(&nrm[ty * 4 + i], s);
    }
    __syncthreads();
#pragma unroll
    for (int i = 0; i < 4; i++) {
        float inv = 1.0f / (1e-6f + sqrtf(nrm[ty * 4 + i]));
#pragma unroll
        for (int j = 0; j < 4; j++)
            g_pre[(size_t)(row0 + ty * 4 + i) * MTR + tx * 4 + j] = acc[i][j] * inv;
    }
}

// ---------------------------------------------------------------------------
// K2a: per-chunk local scan from S=0 -> transfer (B, anyStart).  CHUNK=32.
// ---------------------------------------------------------------------------
__global__ __launch_bounds__(256) void k_chunk(const int* __restrict__ start,
                                               const float* __restrict__ a,
                                               const float* __restrict__ bfreq) {
    __shared__ float sp[CHUNK][MTR];
    __shared__ int ss[CHUNK];
    __shared__ int sAny;
    const int tid = threadIdx.x;
    const int ck = blockIdx.x;
    const int t0 = ck * CHUNK;

    for (int idx = tid; idx < CHUNK * MTR; idx += 256)
        sp[idx >> 6][idx & 63] = g_pre[(size_t)(t0 + (idx >> 6)) * MTR + (idx & 63)];
    if (tid < CHUNK) ss[tid] = (start[t0 + tid] != 0);
    if (tid == 0) sAny = 0;
    __syncthreads();
    if (tid < CHUNK && ss[tid]) atomicOr(&sAny, 1);

    const int m = tid >> 2;
    const float gmag = expf(-fabsf(a[m]));
    float gre[4], gim[4], Sre[4], Sim[4];
#pragma unroll
    for (int q = 0; q < 4; q++) {
        int c = ((tid & 3) << 2) + q;
        float sv, cv; sincosf(bfreq[c], &sv, &cv);
        gre[q] = gmag * cv; gim[q] = gmag * sv;
        Sre[q] = 0.f; Sim[q] = 0.f;
    }
    for (int t = 0; t < CHUNK; t++) {
        float p = sp[t][m];
        float keep = ss[t] ? 0.f : 1.f;
#pragma unroll
        for (int q = 0; q < 4; q++) {
            float r  = keep * (gre[q] * Sre[q] - gim[q] * Sim[q]) + p;
            float im = keep * (gre[q] * Sim[q] + gim[q] * Sre[q]);
            Sre[q] = r; Sim[q] = im;
        }
    }
#pragma unroll
    for (int q = 0; q < 4; q++) {
        int ch = tid * 4 + q;
        g_Bre[(size_t)ck * NCH + ch] = Sre[q];
        g_Bim[(size_t)ck * NCH + ch] = Sim[q];
    }
    __syncthreads();
    if (tid == 0) g_any[ck] = sAny;
}

// ---------------------------------------------------------------------------
// K2b: sequential chain, parallel over channels: 32 blocks x 32 channels.
// ---------------------------------------------------------------------------
#define CB 16
__global__ __launch_bounds__(32) void k_chain(const float* __restrict__ s_re0,
                                              const float* __restrict__ s_im0,
                                              const float* __restrict__ a,
                                              const float* __restrict__ bfreq,
                                              float* stateOut) {
    __shared__ float keep_s[NCHUNK];
    const int ch = blockIdx.x * 32 + threadIdx.x;
    const int m = ch >> 4, c = ch & 15;
    for (int idx = threadIdx.x; idx < NCHUNK; idx += 32)
        keep_s[idx] = g_any[idx] ? 0.f : 1.f;
    __syncthreads();

    const float Amag = expf(-(float)CHUNK * fabsf(a[m]));
    float sv, cv; sincosf((float)CHUNK * bfreq[c], &sv, &cv);
    const float Are = Amag * cv, Aim = Amag * sv;
    float Sre = s_re0[ch], Sim = s_im0[ch];

    for (int kb = 0; kb < NCHUNK; kb += CB) {
        float br[CB], bi[CB];
#pragma unroll
        for (int q = 0; q < CB; q++) {
            br[q] = g_Bre[(size_t)(kb + q) * NCH + ch];
            bi[q] = g_Bim[(size_t)(kb + q) * NCH + ch];
        }
#pragma unroll
        for (int q = 0; q < CB; q++) {
            g_cRe[(size_t)(kb + q) * NCH + ch] = Sre;
            g_cIm[(size_t)(kb + q) * NCH + ch] = Sim;
            float keep = keep_s[kb + q];
            float r  = keep * (Are * Sre - Aim * Sim) + br[q];
            float im = keep * (Are * Sim + Aim * Sre) + bi[q];
            Sre = r; Sim = im;
        }
    }
    stateOut[ch]       = Sre;   // planar: re then im
    stateOut[NCH + ch] = Sim;
}

// ---------------------------------------------------------------------------
// K2c: re-scan with true carry, emit zin as a single fp16 plane.  CHUNK=32.
// ---------------------------------------------------------------------------
__global__ __launch_bounds__(256) void k_emit(const int* __restrict__ start,
                                              const float* __restrict__ a,
                                              const float* __restrict__ bfreq) {
    __shared__ float sp[CHUNK][MTR];
    __shared__ int ss[CHUNK];
    const int tid = threadIdx.x;
    const int ck = blockIdx.x;
    const int t0 = ck * CHUNK;

    for (int idx = tid; idx < CHUNK * MTR; idx += 256)
        sp[idx >> 6][idx & 63] = g_pre[(size_t)(t0 + (idx >> 6)) * MTR + (idx & 63)];
    if (tid < CHUNK) ss[tid] = (start[t0 + tid] != 0);
    __syncthreads();

    const int m = tid >> 2;
    const int cg = tid & 3;
    const float gmag = expf(-fabsf(a[m]));
    float gre[4], gim[4], Sre[4], Sim[4];
#pragma unroll
    for (int q = 0; q < 4; q++) {
        int c = cg * 4 + q;
        float sv, cv; sincosf(bfreq[c], &sv, &cv);
        gre[q] = gmag * cv; gim[q] = gmag * sv;
        int ch = m * CCT + c;
        Sre[q] = g_cRe[(size_t)ck * NCH + ch];
        Sim[q] = g_cIm[(size_t)ck * NCH + ch];
    }
    for (int t = 0; t < CHUNK; t++) {
        float p = sp[t][m];
        float keep = ss[t] ? 0.f : 1.f;
#pragma unroll
        for (int q = 0; q < 4; q++) {
            float r  = keep * (gre[q] * Sre[q] - gim[q] * Sim[q]) + p;
            float im = keep * (gre[q] * Sim[q] + gim[q] * Sre[q]);
            Sre[q] = r; Sim[q] = im;
        }
        size_t base = (size_t)(t0 + t) * DMIX + (size_t)m * 32 + cg * 4;
        *(uint2*)(g_zin16 + base) = make_uint2(
            pack2h(__float2half_rn(Sre[0]), __float2half_rn(Sre[1])),
            pack2h(__float2half_rn(Sre[2]), __float2half_rn(Sre[3])));
        *(uint2*)(g_zin16 + base + 16) = make_uint2(
            pack2h(__float2half_rn(Sim[0]), __float2half_rn(Sim[1])),
            pack2h(__float2half_rn(Sim[2]), __float2half_rn(Sim[3])));
    }
}

// ---------------------------------------------------------------------------
// K3: out = z_in @ Wmix^T + x @ Wskip^T + biases (fp16 2-term mma.sync:
// A fp16, B split hi/lo).  CTA 128x128, 4 warps (2x2), warp tile 64x64.
// XOR-swizzled 64B rows -> conflict-free ldmatrix + cp.async stores.
// ---------------------------------------------------------------------------
#define OFF_A    0
#define OFF_BHI  8192
#define OFF_BLO  16384
#define STG_SZ   24576
#define SM_TOTAL (1024 + 2 * STG_SZ)      // 50176
#define KTILES   (KTOT / 32)              // 96
#define MIXTILES (DMIX / 32)              // 64

__device__ __forceinline__ uint32_t swz(uint32_t row, uint32_t chunk) {
    return row * 64u + ((chunk ^ ((row >> 1) & 3u)) << 4);
}

__global__ __launch_bounds__(128, 2) void k_out_mma(const float* __restrict__ bmix,
                                                    const float* __restrict__ bskip,
                                                    float* __restrict__ out) {
    extern __shared__ char smem[];
    float* bias_s = (float*)smem;
    const uint32_t sb = smem_u32(smem);
    const int tid = threadIdx.x;
    const int lane = tid & 31, wid = tid >> 5;
    const int warp_m = wid & 1, warp_n = wid >> 1;     // 2x2 warps
    const int row0 = blockIdx.y * 128;
    const int col0 = blockIdx.x * 128;

    bias_s[tid] = bmix[col0 + tid] + bskip[col0 + tid];

    float acc[4][8][4];
#pragma unroll
    for (int i = 0; i < 4; i++)
#pragma unroll
        for (int j = 0; j < 8; j++)
#pragma unroll
            for (int q = 0; q < 4; q++) acc[i][j][q] = 0.f;

    // cp.async geometry: 512 16B-chunks per array, 128 threads -> 4 each
    const int rwv[4] = { tid >> 2, (tid + 128) >> 2, (tid + 256) >> 2, (tid + 384) >> 2 };
    const int c16a = tid & 3;
    uint32_t soffv[4];
#pragma unroll
    for (int r = 0; r < 4; r++) soffv[r] = swz((uint32_t)rwv[r], (uint32_t)c16a);

    auto issue_cp = [&](int kt, uint32_t stg) {
        const bool mix = kt < MIXTILES;
        const __half* aP = mix ? g_zin16 : g_x16;
        const __half* bH = mix ? g_wmH : g_wsH;
        const __half* bL = mix ? g_wmL : g_wsL;
        const int ldx = mix ? DMIX : DIN;
        const int kk0 = (mix ? kt * 32 : (kt - MIXTILES) * 32) + c16a * 8;
#pragma unroll
        for (int r = 0; r < 4; r++) {
            size_t gA = (size_t)(row0 + rwv[r]) * ldx + kk0;
            size_t gB = (size_t)(col0 + rwv[r]) * ldx + kk0;
            cp16(stg + OFF_A   + soffv[r], aP + gA);
            cp16(stg + OFF_BHI + soffv[r], bH + gB);
            cp16(stg + OFF_BLO + soffv[r], bL + gB);
        }
        CP_COMMIT();
    };

    issue_cp(0, sb + 1024);

    // ldmatrix lane geometry (swizzle key invariant under row += 16)
    const uint32_t aRow = (uint32_t)(warp_m * 64 + (lane & 15));
    const uint32_t aHi  = (lane >> 4) & 1;
    const uint32_t keyA = (aRow >> 1) & 3;
    const uint32_t bRow = (uint32_t)(warp_n * 64 + (lane & 7) + (((lane >> 4) & 1) << 3));
    const uint32_t bHi  = (lane >> 3) & 1;
    const uint32_t keyB = (bRow >> 1) & 3;

    for (int kt = 0; kt < KTILES; kt++) {
        const uint32_t stg = sb + 1024 + (uint32_t)(kt & 1) * STG_SZ;
        CP_WAIT(0);
        __syncthreads();
        if (kt + 1 < KTILES)
            issue_cp(kt + 1, sb + 1024 + (uint32_t)((kt + 1) & 1) * STG_SZ);

#pragma unroll
        for (int s = 0; s < 2; s++) {
            const uint32_t cA = ((2u * s + aHi) ^ keyA) << 4;
            const uint32_t cB = ((2u * s + bHi) ^ keyB) << 4;
            const uint32_t aAddr = stg + OFF_A   + aRow * 64 + cA;
            const uint32_t bAddr = stg + OFF_BHI + bRow * 64 + cB;
            uint32_t bh[16], bl[16], afr[16];
#pragma unroll
            for (int jj = 0; jj < 4; jj++)
                ldsm4(bh + jj * 4, bAddr + (uint32_t)jj * 1024);
#pragma unroll
            for (int jj = 0; jj < 4; jj++)
                ldsm4(bl + jj * 4, bAddr + (OFF_BLO - OFF_BHI) + (uint32_t)jj * 1024);
#pragma unroll
            for (int i = 0; i < 4; i++)
                ldsm4(afr + i * 4, aAddr + (uint32_t)i * 1024);
#pragma unroll
            for (int i = 0; i < 4; i++)
#pragma unroll
                for (int j = 0; j < 8; j++)
                    mma_f16(acc[i][j], afr + i * 4, bh + j * 2);
#pragma unroll
            for (int i = 0; i < 4; i++)
#pragma unroll
                for (int j = 0; j < 8; j++)
                    mma_f16(acc[i][j], afr + i * 4, bl + j * 2);
        }
    }

    const int r_base = row0 + warp_m * 64 + (lane >> 2);
    const int c_base = warp_n * 64 + (lane & 3) * 2;
#pragma unroll
    for (int i = 0; i < 4; i++) {
#pragma unroll
        for (int j = 0; j < 8; j++) {
            int r = r_base + i * 16;
            int c = c_base + j * 8;
            float b0 = bias_s[c], b1 = bias_s[c + 1];
            float2 v0 = make_float2(acc[i][j][0] + b0, acc[i][j][1] + b1);
            float2 v1 = make_float2(acc[i][j][2] + b0, acc[i][j][3] + b1);
            *(float2*)(out + (size_t)r * DOUT + col0 + c) = v0;
            *(float2*)(out + (size_t)(r + 8) * DOUT + col0 + c) = v1;
        }
    }
}

// ---------------------------------------------------------------------------
// Launch
// ---------------------------------------------------------------------------
extern "C" void kernel_launch(void* const* d_in, const int* in_sizes, int n_in,
                              void* d_out, int out_size) {
    const float* x     = (const float*)d_in[0];
    const float* s_re  = (const float*)d_in[1];
    const float* s_im  = (const float*)d_in[2];
    const int*   start = (const int*)d_in[3];
    const float* Wpre  = (const float*)d_in[5];
    const float* bpre  = (const float*)d_in[6];
    const float* Wskip = (const float*)d_in[7];
    const float* bskip = (const float*)d_in[8];
    const float* Wmix  = (const float*)d_in[9];
    const float* bmix  = (const float*)d_in[10];
    const float* a     = (const float*)d_in[11];
    const float* bf    = (const float*)d_in[12];
    float* out = (float*)d_out;
    float* stateOut = out + (size_t)TT * DOUT;

    cudaFuncSetAttribute(k_out_mma, cudaFuncAttributeMaxDynamicSharedMemorySize, SM_TOTAL);

    k_split<<<(N4_ALL + 255) / 256, 256>>>(x, Wmix, Wskip);
    k_pre<<<TT / 64, 256>>>(x, Wpre, bpre);
    k_chunk<<<NCHUNK, 256>>>(start, a, bf);
    k_chain<<<NCH / 32, 32>>>(s_re, s_im, a, bf, stateOut);
    k_emit<<<NCHUNK, 256>>>(start, a, bf);
    dim3 g3(DOUT / 128, TT / 128);
    k_out_mma<<<g3, 128, SM_TOTAL>>>(bmix, bskip, out);
}